// round 1
// baseline (speedup 1.0000x reference)
#include <cuda_runtime.h>
#include <math.h>

#define N_OBJ 256
#define D_IN  1024
#define C_EMB 256
#define H_DIM 1024
#define O_DIM 1024
#define R_DIM 51
#define NP    (N_OBJ * N_OBJ)   /* 65536 edge rows */
#define BN_EPS 1e-5f
#define SLOPE  0.01f

// ---------------- scratch (static device globals; no allocation) ----------------
__device__ float g_h[(size_t)NP * H_DIM];        // 256 MB: post-LeakyReLU h
__device__ float g_hi[N_OBJ * H_DIM];            // feats @ W1[:D]
__device__ float g_hj[N_OBJ * H_DIM];            // feats @ W1[D:2D]
__device__ float g_psum[32 * H_DIM];             // BN partial sums (32 row chunks)
__device__ float g_psq[32 * H_DIM];              // BN partial sum of squares
__device__ float g_scale[H_DIM];                 // gamma * rsqrt(var+eps)
__device__ float g_shift[H_DIM];                 // beta - mean*scale

// ---------------- generic 128x128x8 SIMT fp32 GEMM, 256 threads, 8x8/thread ----
// MODE 0: C(which? g_hj : g_hi) = A[256,1024] @ B[1024,1024]
// MODE 1: g_h = leakyrelu(A(cemb)[65536,256] @ B(W1c)[256,1024] + hi + hj + b1)
// MODE 2: Cext(feat) = (g_h * scale + shift)[65536,1024] @ B(W2)[1024,1024] + b2
template<int MODE>
__launch_bounds__(256)
__global__ void gemm128(const float* __restrict__ Aext,
                        const float* __restrict__ B,
                        float* __restrict__ Cext,
                        const float* __restrict__ bias,
                        int which)
{
    constexpr int LDA = (MODE == 1) ? C_EMB : 1024;
    constexpr int KD  = (MODE == 1) ? C_EMB : 1024;
    const int LDB = 1024, LDC = 1024;

    const float* A = (MODE == 2) ? g_h : Aext;
    float* C;
    if (MODE == 0)      C = which ? g_hj : g_hi;
    else if (MODE == 1) C = g_h;
    else                C = Cext;

    __shared__ float As[8][132];   // padded: conflict-free transposed stores
    __shared__ float Bs[8][128];

    const int tid = threadIdx.x;
    const int tx = tid & 15, ty = tid >> 4;
    const int m0 = blockIdx.y * 128, n0 = blockIdx.x * 128;

    float acc[8][8];
#pragma unroll
    for (int i = 0; i < 8; i++)
#pragma unroll
        for (int j = 0; j < 8; j++) acc[i][j] = 0.f;

    const int ar = tid >> 1;          // 0..127 tile row
    const int ak = (tid & 1) * 4;     // 0 or 4
    const int bk = tid >> 5;          // 0..7
    const int bc = (tid & 31) * 4;    // 0..124

    const float* Aptr = A + (size_t)(m0 + ar) * LDA + ak;
    const float* Bptr = B + (size_t)bk * LDB + n0 + bc;

    for (int k0 = 0; k0 < KD; k0 += 8) {
        float4 av = *(const float4*)(Aptr + k0);
        if (MODE == 2) {
            float4 sc = *(const float4*)(g_scale + k0 + ak);
            float4 sh = *(const float4*)(g_shift + k0 + ak);
            av.x = av.x * sc.x + sh.x;
            av.y = av.y * sc.y + sh.y;
            av.z = av.z * sc.z + sh.z;
            av.w = av.w * sc.w + sh.w;
        }
        float4 bv = *(const float4*)(Bptr + (size_t)k0 * LDB);
        As[ak + 0][ar] = av.x;
        As[ak + 1][ar] = av.y;
        As[ak + 2][ar] = av.z;
        As[ak + 3][ar] = av.w;
        *(float4*)(&Bs[bk][bc]) = bv;
        __syncthreads();
#pragma unroll
        for (int kk = 0; kk < 8; kk++) {
            float a[8], b[8];
#pragma unroll
            for (int i = 0; i < 8; i++) a[i] = As[kk][ty * 8 + i];
#pragma unroll
            for (int j = 0; j < 8; j++) b[j] = Bs[kk][tx * 8 + j];
#pragma unroll
            for (int i = 0; i < 8; i++)
#pragma unroll
                for (int j = 0; j < 8; j++) acc[i][j] += a[i] * b[j];
        }
        __syncthreads();
    }

#pragma unroll
    for (int i = 0; i < 8; i++) {
        const int row = m0 + ty * 8 + i;
#pragma unroll
        for (int j = 0; j < 8; j++) {
            const int col = n0 + tx * 8 + j;
            float v = acc[i][j];
            if (MODE == 1) {
                const int n = row >> 8, mm = row & 255;
                v += g_hi[n * H_DIM + col] + g_hj[mm * H_DIM + col] + bias[col];
                v = (v >= 0.f) ? v : SLOPE * v;
            } else if (MODE == 2) {
                v += bias[col];
            }
            C[(size_t)row * LDC + col] = v;
        }
    }
}

// ---------------- BN stats: deterministic 2-stage reduction --------------------
// grid (8, 32), 128 threads: block (bx,by) handles channels bx*128..+128 over
// row chunk by*2048..+2048.
__global__ void stats_partial()
{
    const int ch = blockIdx.x * 128 + threadIdx.x;
    const int rb = blockIdx.y;
    const float* p = g_h + (size_t)rb * 2048 * H_DIM + ch;
    float s = 0.f, q = 0.f;
#pragma unroll 4
    for (int r = 0; r < 2048; r++) {
        float v = p[(size_t)r * H_DIM];
        s += v;
        q += v * v;
    }
    g_psum[rb * H_DIM + ch] = s;
    g_psq[rb * H_DIM + ch] = q;
}

__global__ void finalize_bn(const float* __restrict__ gamma,
                            const float* __restrict__ beta)
{
    const int c = blockIdx.x * 256 + threadIdx.x;
    if (c < H_DIM) {
        float s = 0.f, q = 0.f;
#pragma unroll
        for (int i = 0; i < 32; i++) {
            s += g_psum[i * H_DIM + c];
            q += g_psq[i * H_DIM + c];
        }
        const float inv = 1.0f / (float)NP;
        const float mean = s * inv;
        const float var  = q * inv - mean * mean;
        const float sc = gamma[c] * rsqrtf(var + BN_EPS);
        g_scale[c] = sc;
        g_shift[c] = beta[c] - mean * sc;
    }
}

// ---------------- attention: conf = softmax(feat @ w_att + b), enhanced -------
// one block per n (256 blocks, 256 threads)
__global__ void attn_aggregate(const float* __restrict__ feat,
                               const float* __restrict__ w_att,
                               const float* __restrict__ b_att,
                               float* __restrict__ enhanced)
{
    __shared__ float conf[N_OBJ];
    __shared__ float red[256];
    __shared__ float watt_s[O_DIM];

    const int n = blockIdx.x;
    const int tid = threadIdx.x;
    const int warp = tid >> 5, lane = tid & 31;
    const float* frow = feat + (size_t)n * N_OBJ * O_DIM;

    for (int i = tid; i < O_DIM; i += 256) watt_s[i] = w_att[i];
    __syncthreads();

    // conf[m] = dot(feat[n,m,:], w_att) + b_att
    for (int m = warp; m < N_OBJ; m += 8) {
        const float* f = frow + (size_t)m * O_DIM;
        float s = 0.f;
        for (int i = lane; i < O_DIM; i += 32) s += f[i] * watt_s[i];
#pragma unroll
        for (int o = 16; o; o >>= 1) s += __shfl_xor_sync(0xFFFFFFFFu, s, o);
        if (lane == 0) conf[m] = s + b_att[0];
    }
    __syncthreads();

    // softmax over 256 values
    float v = conf[tid];
    red[tid] = v;
    __syncthreads();
    for (int o = 128; o; o >>= 1) {
        if (tid < o) red[tid] = fmaxf(red[tid], red[tid + o]);
        __syncthreads();
    }
    const float mx = red[0];
    __syncthreads();
    const float e = expf(v - mx);
    red[tid] = e;
    __syncthreads();
    for (int o = 128; o; o >>= 1) {
        if (tid < o) red[tid] += red[tid + o];
        __syncthreads();
    }
    const float p = e / red[0];
    __syncthreads();
    conf[tid] = p;
    __syncthreads();

    // enhanced[n,:] = sum_m conf[m] * feat[n,m,:]   (each thread 4 cols)
    float acc[4] = {0.f, 0.f, 0.f, 0.f};
    for (int m = 0; m < N_OBJ; m++) {
        const float pm = conf[m];
        const float* f = frow + (size_t)m * O_DIM;
#pragma unroll
        for (int j = 0; j < 4; j++) acc[j] += pm * f[tid + j * 256];
    }
#pragma unroll
    for (int j = 0; j < 4; j++)
        enhanced[(size_t)n * O_DIM + tid + j * 256] = acc[j];
}

// ---------------- relation_cls = feat @ W_rel + b_rel  [65536,1024]@[1024,51] --
// block: 128 rows; 256 threads: (rowpair = tid>>2) x (colgroup = tid&3 -> 13 cols)
__launch_bounds__(256)
__global__ void relation_kernel(const float* __restrict__ feat,
                                const float* __restrict__ Wrel,
                                const float* __restrict__ brel,
                                float* __restrict__ out)
{
    __shared__ float As[128][65];
    __shared__ float Bs[64][52];

    const int tid = threadIdx.x;
    const int cg = tid & 3;
    const int rh = tid >> 2;          // 0..63
    const int r0 = rh * 2, r1 = r0 + 1;
    const int row0 = blockIdx.x * 128;
    const int c0 = cg * 13;

    float acc0[13], acc1[13];
#pragma unroll
    for (int j = 0; j < 13; j++) { acc0[j] = 0.f; acc1[j] = 0.f; }

    for (int kb = 0; kb < O_DIM; kb += 64) {
        // A tile: 128x64 (2048 float4, 8 per thread)
#pragma unroll
        for (int i = 0; i < 8; i++) {
            const int f = tid + i * 256;
            const int r = f >> 4;
            const int kk = (f & 15) * 4;
            float4 v = *(const float4*)(feat + (size_t)(row0 + r) * O_DIM + kb + kk);
            As[r][kk + 0] = v.x;
            As[r][kk + 1] = v.y;
            As[r][kk + 2] = v.z;
            As[r][kk + 3] = v.w;
        }
        // B tile: 64x51
        for (int i = tid; i < 64 * R_DIM; i += 256) {
            const int k = i / R_DIM, c = i % R_DIM;
            Bs[k][c] = Wrel[(size_t)(kb + k) * R_DIM + c];
        }
        __syncthreads();
#pragma unroll 4
        for (int k = 0; k < 64; k++) {
            const float a0 = As[r0][k], a1 = As[r1][k];
#pragma unroll
            for (int j = 0; j < 13; j++) {
                const int c = c0 + j;
                if (c < R_DIM) {
                    const float b = Bs[k][c];
                    acc0[j] += a0 * b;
                    acc1[j] += a1 * b;
                }
            }
        }
        __syncthreads();
    }
#pragma unroll
    for (int j = 0; j < 13; j++) {
        const int c = c0 + j;
        if (c < R_DIM) {
            out[(size_t)(row0 + r0) * R_DIM + c] = acc0[j] + brel[c];
            out[(size_t)(row0 + r1) * R_DIM + c] = acc1[j] + brel[c];
        }
    }
}

// ---------------- launcher ----------------------------------------------------
extern "C" void kernel_launch(void* const* d_in, const int* in_sizes, int n_in,
                              void* d_out, int out_size)
{
    const float* feats = (const float*)d_in[0];   // [256,1024]
    const float* cemb  = (const float*)d_in[1];   // [256,256,256]
    const float* W1    = (const float*)d_in[2];   // [2304,1024]
    const float* b1    = (const float*)d_in[3];
    const float* gamma = (const float*)d_in[4];
    const float* beta  = (const float*)d_in[5];
    const float* W2    = (const float*)d_in[6];   // [1024,1024]
    const float* b2    = (const float*)d_in[7];
    const float* watt  = (const float*)d_in[8];   // [1024]
    const float* batt  = (const float*)d_in[9];   // [1]
    const float* Wrel  = (const float*)d_in[10];  // [1024,51]
    const float* brel  = (const float*)d_in[11];  // [51]

    float* out      = (float*)d_out;
    float* feat     = out;                                  // 256*256*1024
    float* enhanced = out + (size_t)NP * O_DIM;             // 256*1024
    float* relation = enhanced + (size_t)N_OBJ * O_DIM;     // 256*256*51

    dim3 blk(256);

    // hi = feats @ W1[:D], hj = feats @ W1[D:2D]
    gemm128<0><<<dim3(8, 2), blk>>>(feats, W1, nullptr, nullptr, 0);
    gemm128<0><<<dim3(8, 2), blk>>>(feats, W1 + (size_t)D_IN * H_DIM, nullptr, nullptr, 1);

    // h = leakyrelu(cemb @ W1[2D:] + hi + hj + b1)  -> g_h
    gemm128<1><<<dim3(8, 512), blk>>>(cemb, W1 + (size_t)2 * D_IN * H_DIM, nullptr, b1, 0);

    // BatchNorm stats (deterministic)
    stats_partial<<<dim3(8, 32), 128>>>();
    finalize_bn<<<4, 256>>>(gamma, beta);

    // feat = (g_h*scale + shift) @ W2 + b2
    gemm128<2><<<dim3(8, 512), blk>>>(nullptr, W2, feat, b2, 0);

    // attention softmax + aggregation
    attn_aggregate<<<N_OBJ, 256>>>(feat, watt, batt, enhanced);

    // relation classifier
    relation_kernel<<<NP / 128, 256>>>(feat, Wrel, brel, relation);
}

// round 7
// speedup vs baseline: 1.6057x; 1.6057x over previous
#include <cuda_runtime.h>
#include <cuda_bf16.h>
#include <cstdint>
#include <math.h>

#define N_OBJ 256
#define D_IN  1024
#define C_EMB 256
#define H_DIM 1024
#define O_DIM 1024
#define R_DIM 51
#define NP    (N_OBJ * N_OBJ)   /* 65536 edge rows */
#define BN_EPS 1e-5f
#define SLOPE  0.01f
#define RB_STATS 256

// ---------------- scratch (static device globals; no allocation) ---------------
__device__ float g_h[(size_t)NP * H_DIM];                 // fp32 post-LeakyReLU h
__device__ __align__(128) __nv_bfloat16 g_hb_hi[(size_t)NP * H_DIM];  // BN(h) split
__device__ __align__(128) __nv_bfloat16 g_hb_lo[(size_t)NP * H_DIM];
__device__ __align__(128) __nv_bfloat16 g_W2t_hi[O_DIM * H_DIM];      // W2^T split [j][k]
__device__ __align__(128) __nv_bfloat16 g_W2t_lo[O_DIM * H_DIM];
__device__ float g_hi[N_OBJ * H_DIM];
__device__ float g_hj[N_OBJ * H_DIM];
__device__ float g_ps[RB_STATS * H_DIM];
__device__ float g_pq[RB_STATS * H_DIM];
__device__ float g_scale[H_DIM];
__device__ float g_shift[H_DIM];

__device__ __forceinline__ void mma_bf16(float* c, const uint32_t* a, const uint32_t* b) {
    asm volatile("mma.sync.aligned.m16n8k16.row.col.f32.bf16.bf16.f32 "
                 "{%0,%1,%2,%3}, {%4,%5,%6,%7}, {%8,%9}, {%0,%1,%2,%3};"
                 : "+f"(c[0]), "+f"(c[1]), "+f"(c[2]), "+f"(c[3])
                 : "r"(a[0]), "r"(a[1]), "r"(a[2]), "r"(a[3]), "r"(b[0]), "r"(b[1]));
}
__device__ __forceinline__ void split_bf16(float v, __nv_bfloat16& h, __nv_bfloat16& l) {
    h = __float2bfloat16_rn(v);
    l = __float2bfloat16_rn(v - __bfloat162float(h));
}

// ---------------- round-1 verbatim: 128x128x8 SIMT fp32 GEMM -------------------
// MODE 0: C(which? g_hj : g_hi) = A[256,1024] @ B[1024,1024]
// MODE 1: g_h = leakyrelu(A(cemb)[65536,256] @ B(W1c)[256,1024] + hi + hj + b1)
template<int MODE>
__launch_bounds__(256)
__global__ void gemm128(const float* __restrict__ A,
                        const float* __restrict__ B,
                        const float* __restrict__ bias,
                        int which)
{
    constexpr int LDA = (MODE == 1) ? C_EMB : 1024;
    constexpr int KD  = (MODE == 1) ? C_EMB : 1024;

    float* C;
    if (MODE == 0) C = which ? g_hj : g_hi;
    else           C = g_h;

    __shared__ float As[8][132];
    __shared__ float Bs[8][128];

    const int tid = threadIdx.x;
    const int tx = tid & 15, ty = tid >> 4;
    const int m0 = blockIdx.y * 128, n0 = blockIdx.x * 128;

    float acc[8][8];
#pragma unroll
    for (int i = 0; i < 8; i++)
#pragma unroll
        for (int j = 0; j < 8; j++) acc[i][j] = 0.f;

    const int ar = tid >> 1, ak = (tid & 1) * 4;
    const int bk = tid >> 5, bc = (tid & 31) * 4;
    const float* Aptr = A + (size_t)(m0 + ar) * LDA + ak;
    const float* Bptr = B + (size_t)bk * 1024 + n0 + bc;

    for (int k0 = 0; k0 < KD; k0 += 8) {
        float4 av = *(const float4*)(Aptr + k0);
        float4 bv = *(const float4*)(Bptr + (size_t)k0 * 1024);
        As[ak][ar] = av.x; As[ak + 1][ar] = av.y; As[ak + 2][ar] = av.z; As[ak + 3][ar] = av.w;
        *(float4*)(&Bs[bk][bc]) = bv;
        __syncthreads();
#pragma unroll
        for (int kk = 0; kk < 8; kk++) {
            float a[8], b[8];
#pragma unroll
            for (int i = 0; i < 8; i++) a[i] = As[kk][ty * 8 + i];
#pragma unroll
            for (int j = 0; j < 8; j++) b[j] = Bs[kk][tx * 8 + j];
#pragma unroll
            for (int i = 0; i < 8; i++)
#pragma unroll
                for (int j = 0; j < 8; j++) acc[i][j] += a[i] * b[j];
        }
        __syncthreads();
    }

#pragma unroll
    for (int i = 0; i < 8; i++) {
        const int row = m0 + ty * 8 + i;
#pragma unroll
        for (int j = 0; j < 8; j++) {
            const int col = n0 + tx * 8 + j;
            float v = acc[i][j];
            if (MODE == 1) {
                const int n = row >> 8, mm = row & 255;
                v += g_hi[n * H_DIM + col] + g_hj[mm * H_DIM + col] + bias[col];
                v = (v >= 0.f) ? v : SLOPE * v;
            }
            C[(size_t)row * 1024 + col] = v;
        }
    }
}

// ---------------- BN stats on fp32 g_h (deterministic) -------------------------
__global__ void stats_f32()
{
    const int cp = blockIdx.x * 256 + threadIdx.x;  // 0..511 column pairs
    const int rb = blockIdx.y;                       // 0..255 chunks of 256 rows
    const int c0 = cp * 2;
    float s0 = 0.f, s1 = 0.f, q0 = 0.f, q1 = 0.f;
#pragma unroll 4
    for (int r = 0; r < 256; r++) {
        const float2 v = *(const float2*)&g_h[(size_t)(rb * 256 + r) * H_DIM + c0];
        s0 += v.x; q0 += v.x * v.x;
        s1 += v.y; q1 += v.y * v.y;
    }
    g_ps[rb * H_DIM + c0] = s0; g_ps[rb * H_DIM + c0 + 1] = s1;
    g_pq[rb * H_DIM + c0] = q0; g_pq[rb * H_DIM + c0 + 1] = q1;
}

__global__ void finalize_bn(const float* __restrict__ gamma, const float* __restrict__ beta)
{
    const int c = blockIdx.x * 256 + threadIdx.x;
    float s = 0.f, q = 0.f;
#pragma unroll
    for (int i = 0; i < RB_STATS; i++) { s += g_ps[i * H_DIM + c]; q += g_pq[i * H_DIM + c]; }
    const float inv = 1.0f / (float)NP;
    const float mean = s * inv;
    const float var = q * inv - mean * mean;
    const float sc = gamma[c] * rsqrtf(var + BN_EPS);
    g_scale[c] = sc;
    g_shift[c] = beta[c] - mean * sc;
}

// ---------------- BN-apply + split h -> bf16 hi/lo planes ----------------------
__global__ void convert_h()
{
    const size_t i = ((size_t)blockIdx.x * 256 + threadIdx.x) * 4;
    if (i >= (size_t)NP * H_DIM) return;
    const int col = (int)(i & (H_DIM - 1));
    const float4 h4 = *(const float4*)&g_h[i];
    const float4 sc = *(const float4*)&g_scale[col];
    const float4 sh = *(const float4*)&g_shift[col];
    float v[4] = { h4.x * sc.x + sh.x, h4.y * sc.y + sh.y,
                   h4.z * sc.z + sh.z, h4.w * sc.w + sh.w };
    uint32_t hw[2], lw[2];
#pragma unroll
    for (int p = 0; p < 2; p++) {
        __nv_bfloat16 h0, l0, h1, l1;
        split_bf16(v[2 * p], h0, l0);
        split_bf16(v[2 * p + 1], h1, l1);
        hw[p] = (uint32_t)__bfloat16_as_ushort(h0) | ((uint32_t)__bfloat16_as_ushort(h1) << 16);
        lw[p] = (uint32_t)__bfloat16_as_ushort(l0) | ((uint32_t)__bfloat16_as_ushort(l1) << 16);
    }
    *(uint2*)((char*)g_hb_hi + i * 2) = make_uint2(hw[0], hw[1]);
    *(uint2*)((char*)g_hb_lo + i * 2) = make_uint2(lw[0], lw[1]);
}

// ---------------- W2^T split (naive, auditable) --------------------------------
__global__ void split_W2t(const float* __restrict__ W2)
{
    const int j = blockIdx.x;
#pragma unroll
    for (int it = 0; it < 4; it++) {
        const int k = it * 256 + threadIdx.x;
        __nv_bfloat16 h, l;
        split_bf16(W2[(size_t)k * O_DIM + j], h, l);
        g_W2t_hi[(size_t)j * H_DIM + k] = h;
        g_W2t_lo[(size_t)j * H_DIM + k] = l;
    }
}

// ---------------- HMMA bf16x3 GEMM2: feat = BN(h) @ W2 + b2 --------------------
// Direct-LDS fragments (PTX m16n8k16 mapping), TK=16, reg-staged double buffer.
#define TK2   16
#define APAD2 24
__global__ __launch_bounds__(256)
void mma_feat(const float* __restrict__ b2, float* __restrict__ out_feat)
{
    __shared__ __align__(16) __nv_bfloat16 sAhi[2][128][APAD2];
    __shared__ __align__(16) __nv_bfloat16 sAlo[2][128][APAD2];
    __shared__ __align__(16) __nv_bfloat16 sBhi[2][128][APAD2];
    __shared__ __align__(16) __nv_bfloat16 sBlo[2][128][APAD2];

    const int tid = threadIdx.x;
    const int lane = tid & 31, wid = tid >> 5;
    const int m0 = blockIdx.y * 128, n0 = blockIdx.x * 128;
    const int NC = H_DIM / TK2;           // 64

    const int m_base = (wid >> 2) * 64;
    const int n_base = (wid & 3) * 32;
    const int fr = lane >> 2;             // fragment row 0..7
    const int fk = (lane & 3) * 2;        // fragment k 0,2,4,6

    const int ld_row = tid >> 1, ld_c = (tid & 1) * 8;

    float acc[4][4][4];
#pragma unroll
    for (int i = 0; i < 4; i++)
#pragma unroll
        for (int j = 0; j < 4; j++)
#pragma unroll
            for (int r = 0; r < 4; r++) acc[i][j][r] = 0.f;

    // preload chunk 0 into buffer 0
    {
        const size_t ka = (size_t)(m0 + ld_row) * H_DIM + ld_c;
        const size_t kb = (size_t)(n0 + ld_row) * H_DIM + ld_c;
        *(uint4*)&sAhi[0][ld_row][ld_c] = *(const uint4*)(g_hb_hi + ka);
        *(uint4*)&sAlo[0][ld_row][ld_c] = *(const uint4*)(g_hb_lo + ka);
        *(uint4*)&sBhi[0][ld_row][ld_c] = *(const uint4*)(g_W2t_hi + kb);
        *(uint4*)&sBlo[0][ld_row][ld_c] = *(const uint4*)(g_W2t_lo + kb);
    }
    __syncthreads();

    for (int c = 0; c < NC; c++) {
        const int cur = c & 1, nxt = cur ^ 1;
        uint4 pa, pb, pc, pd;
        if (c + 1 < NC) {
            const size_t ka = (size_t)(m0 + ld_row) * H_DIM + (c + 1) * TK2 + ld_c;
            const size_t kb = (size_t)(n0 + ld_row) * H_DIM + (c + 1) * TK2 + ld_c;
            pa = *(const uint4*)(g_hb_hi + ka);
            pb = *(const uint4*)(g_hb_lo + ka);
            pc = *(const uint4*)(g_W2t_hi + kb);
            pd = *(const uint4*)(g_W2t_lo + kb);
        }

        uint32_t a_hi[4][4], a_lo[4][4], b_hi[4][2], b_lo[4][2];
#pragma unroll
        for (int mt = 0; mt < 4; mt++) {
            const int r0 = m_base + mt * 16 + fr;
            a_hi[mt][0] = *(const uint32_t*)&sAhi[cur][r0    ][fk];
            a_hi[mt][1] = *(const uint32_t*)&sAhi[cur][r0 + 8][fk];
            a_hi[mt][2] = *(const uint32_t*)&sAhi[cur][r0    ][fk + 8];
            a_hi[mt][3] = *(const uint32_t*)&sAhi[cur][r0 + 8][fk + 8];
            a_lo[mt][0] = *(const uint32_t*)&sAlo[cur][r0    ][fk];
            a_lo[mt][1] = *(const uint32_t*)&sAlo[cur][r0 + 8][fk];
            a_lo[mt][2] = *(const uint32_t*)&sAlo[cur][r0    ][fk + 8];
            a_lo[mt][3] = *(const uint32_t*)&sAlo[cur][r0 + 8][fk + 8];
        }
#pragma unroll
        for (int nt = 0; nt < 4; nt++) {
            const int n = n_base + nt * 8 + fr;
            b_hi[nt][0] = *(const uint32_t*)&sBhi[cur][n][fk];
            b_hi[nt][1] = *(const uint32_t*)&sBhi[cur][n][fk + 8];
            b_lo[nt][0] = *(const uint32_t*)&sBlo[cur][n][fk];
            b_lo[nt][1] = *(const uint32_t*)&sBlo[cur][n][fk + 8];
        }
#pragma unroll
        for (int mt = 0; mt < 4; mt++)
#pragma unroll
            for (int nt = 0; nt < 4; nt++) {
                mma_bf16(acc[mt][nt], a_hi[mt], b_hi[nt]);
                mma_bf16(acc[mt][nt], a_hi[mt], b_lo[nt]);
                mma_bf16(acc[mt][nt], a_lo[mt], b_hi[nt]);
            }

        if (c + 1 < NC) {
            *(uint4*)&sAhi[nxt][ld_row][ld_c] = pa;
            *(uint4*)&sAlo[nxt][ld_row][ld_c] = pb;
            *(uint4*)&sBhi[nxt][ld_row][ld_c] = pc;
            *(uint4*)&sBlo[nxt][ld_row][ld_c] = pd;
        }
        __syncthreads();
    }

    // epilogue: c0,c1 -> row fr; c2,c3 -> row fr+8
#pragma unroll
    for (int mt = 0; mt < 4; mt++)
#pragma unroll
        for (int nt = 0; nt < 4; nt++) {
            const int col0 = n0 + n_base + nt * 8 + fk;
#pragma unroll
            for (int half = 0; half < 2; half++) {
                const int row = m0 + m_base + mt * 16 + fr + half * 8;
                const float v0 = acc[mt][nt][half * 2]     + b2[col0];
                const float v1 = acc[mt][nt][half * 2 + 1] + b2[col0 + 1];
                *(float2*)(out_feat + (size_t)row * O_DIM + col0) = make_float2(v0, v1);
            }
        }
}

// ---------------- round-1 verbatim: attention ----------------------------------
__global__ void attn_aggregate(const float* __restrict__ feat,
                               const float* __restrict__ w_att,
                               const float* __restrict__ b_att,
                               float* __restrict__ enhanced)
{
    __shared__ float conf[N_OBJ];
    __shared__ float red[256];
    __shared__ float watt_s[O_DIM];

    const int n = blockIdx.x;
    const int tid = threadIdx.x;
    const int warp = tid >> 5, lane = tid & 31;
    const float* frow = feat + (size_t)n * N_OBJ * O_DIM;

    for (int i = tid; i < O_DIM; i += 256) watt_s[i] = w_att[i];
    __syncthreads();

    for (int m = warp; m < N_OBJ; m += 8) {
        const float* f = frow + (size_t)m * O_DIM;
        float s = 0.f;
        for (int i = lane; i < O_DIM; i += 32) s += f[i] * watt_s[i];
#pragma unroll
        for (int o = 16; o; o >>= 1) s += __shfl_xor_sync(0xFFFFFFFFu, s, o);
        if (lane == 0) conf[m] = s + b_att[0];
    }
    __syncthreads();

    float v = conf[tid];
    red[tid] = v;
    __syncthreads();
    for (int o = 128; o; o >>= 1) {
        if (tid < o) red[tid] = fmaxf(red[tid], red[tid + o]);
        __syncthreads();
    }
    const float mx = red[0];
    __syncthreads();
    const float e = expf(v - mx);
    red[tid] = e;
    __syncthreads();
    for (int o = 128; o; o >>= 1) {
        if (tid < o) red[tid] += red[tid + o];
        __syncthreads();
    }
    const float p = e / red[0];
    __syncthreads();
    conf[tid] = p;
    __syncthreads();

    float acc[4] = {0.f, 0.f, 0.f, 0.f};
    for (int m = 0; m < N_OBJ; m++) {
        const float pm = conf[m];
        const float* f = frow + (size_t)m * O_DIM;
#pragma unroll
        for (int j = 0; j < 4; j++) acc[j] += pm * f[tid + j * 256];
    }
#pragma unroll
    for (int j = 0; j < 4; j++)
        enhanced[(size_t)n * O_DIM + tid + j * 256] = acc[j];
}

// ---------------- round-1 verbatim: relation -----------------------------------
__launch_bounds__(256)
__global__ void relation_kernel(const float* __restrict__ feat,
                                const float* __restrict__ Wrel,
                                const float* __restrict__ brel,
                                float* __restrict__ out)
{
    __shared__ float As[128][65];
    __shared__ float Bs[64][52];

    const int tid = threadIdx.x;
    const int cg = tid & 3;
    const int rh = tid >> 2;
    const int r0 = rh * 2, r1 = r0 + 1;
    const int row0 = blockIdx.x * 128;
    const int c0 = cg * 13;

    float acc0[13], acc1[13];
#pragma unroll
    for (int j = 0; j < 13; j++) { acc0[j] = 0.f; acc1[j] = 0.f; }

    for (int kb = 0; kb < O_DIM; kb += 64) {
#pragma unroll
        for (int i = 0; i < 8; i++) {
            const int f = tid + i * 256;
            const int r = f >> 4;
            const int kk = (f & 15) * 4;
            float4 v = *(const float4*)(feat + (size_t)(row0 + r) * O_DIM + kb + kk);
            As[r][kk + 0] = v.x; As[r][kk + 1] = v.y; As[r][kk + 2] = v.z; As[r][kk + 3] = v.w;
        }
        for (int i = tid; i < 64 * R_DIM; i += 256) {
            const int k = i / R_DIM, c = i % R_DIM;
            Bs[k][c] = Wrel[(size_t)(kb + k) * R_DIM + c];
        }
        __syncthreads();
#pragma unroll 4
        for (int k = 0; k < 64; k++) {
            const float a0 = As[r0][k], a1 = As[r1][k];
#pragma unroll
            for (int j = 0; j < 13; j++) {
                const int c = c0 + j;
                if (c < R_DIM) {
                    const float b = Bs[k][c];
                    acc0[j] += a0 * b;
                    acc1[j] += a1 * b;
                }
            }
        }
        __syncthreads();
    }
#pragma unroll
    for (int j = 0; j < 13; j++) {
        const int c = c0 + j;
        if (c < R_DIM) {
            out[(size_t)(row0 + r0) * R_DIM + c] = acc0[j] + brel[c];
            out[(size_t)(row0 + r1) * R_DIM + c] = acc1[j] + brel[c];
        }
    }
}

// ---------------- launcher ------------------------------------------------------
extern "C" void kernel_launch(void* const* d_in, const int* in_sizes, int n_in,
                              void* d_out, int out_size)
{
    const float* feats = (const float*)d_in[0];
    const float* cemb  = (const float*)d_in[1];
    const float* W1    = (const float*)d_in[2];
    const float* b1    = (const float*)d_in[3];
    const float* gamma = (const float*)d_in[4];
    const float* beta  = (const float*)d_in[5];
    const float* W2    = (const float*)d_in[6];
    const float* b2    = (const float*)d_in[7];
    const float* watt  = (const float*)d_in[8];
    const float* batt  = (const float*)d_in[9];
    const float* Wrel  = (const float*)d_in[10];
    const float* brel  = (const float*)d_in[11];

    float* out      = (float*)d_out;
    float* feat     = out;
    float* enhanced = out + (size_t)NP * O_DIM;
    float* relation = enhanced + (size_t)N_OBJ * O_DIM;

    // hi = feats @ W1[:D], hj = feats @ W1[D:2D]   (round-1 path)
    gemm128<0><<<dim3(8, 2), 256>>>(feats, W1, nullptr, 0);
    gemm128<0><<<dim3(8, 2), 256>>>(feats, W1 + (size_t)D_IN * H_DIM, nullptr, 1);

    // g_h = leakyrelu(cemb @ W1[2D:] + hi + hj + b1)   (round-1 path, fp32)
    gemm128<1><<<dim3(8, 512), 256>>>(cemb, W1 + (size_t)2 * D_IN * H_DIM, b1, 0);

    // BN stats
    stats_f32<<<dim3(2, RB_STATS), 256>>>();
    finalize_bn<<<4, 256>>>(gamma, beta);

    // BN-apply + split to bf16 planes; W2^T split
    convert_h<<<(int)(((size_t)NP * H_DIM / 4 + 255) / 256), 256>>>();
    split_W2t<<<O_DIM, 256>>>(W2);

    // GEMM2 on tensor cores: feat = BN(h) @ W2 + b2
    mma_feat<<<dim3(8, 512), 256>>>(b2, feat);

    // round-1 attention + relation (from feat)
    attn_aggregate<<<N_OBJ, 256>>>(feat, watt, batt, enhanced);
    relation_kernel<<<NP / 128, 256>>>(feat, Wrel, brel, relation);
}

// round 9
// speedup vs baseline: 1.8821x; 1.1722x over previous
#include <cuda_runtime.h>
#include <cuda_bf16.h>
#include <cstdint>
#include <math.h>

#define N_OBJ 256
#define D_IN  1024
#define C_EMB 256
#define H_DIM 1024
#define O_DIM 1024
#define R_DIM 51
#define NP    (N_OBJ * N_OBJ)   /* 65536 edge rows */
#define BN_EPS 1e-5f
#define SLOPE  0.01f
#define RB_STATS 256

// ---------------- scratch (static device globals; no allocation) ---------------
// RULE (root cause of rounds 2-8): these symbols are ONLY referenced inside
// device code. NEVER passed as kernel arguments from kernel_launch (host code
// would pass the host shadow address; ATS on GB300 makes it read zeros).
__device__ float g_h[(size_t)NP * H_DIM];                 // fp32 post-LeakyReLU h
__device__ __align__(128) __nv_bfloat16 g_c_hi[(size_t)NP * C_EMB];   // cemb split
__device__ __align__(128) __nv_bfloat16 g_c_lo[(size_t)NP * C_EMB];
__device__ __align__(128) __nv_bfloat16 g_W1t_hi[H_DIM * C_EMB];      // W1c^T split [j][k]
__device__ __align__(128) __nv_bfloat16 g_W1t_lo[H_DIM * C_EMB];
__device__ __align__(128) __nv_bfloat16 g_hb_hi[(size_t)NP * H_DIM];  // BN(h) split
__device__ __align__(128) __nv_bfloat16 g_hb_lo[(size_t)NP * H_DIM];
__device__ __align__(128) __nv_bfloat16 g_W2t_hi[O_DIM * H_DIM];      // W2^T split [j][k]
__device__ __align__(128) __nv_bfloat16 g_W2t_lo[O_DIM * H_DIM];
__device__ float g_hi[N_OBJ * H_DIM];
__device__ float g_hj[N_OBJ * H_DIM];
__device__ float g_ps[RB_STATS * H_DIM];
__device__ float g_pq[RB_STATS * H_DIM];
__device__ float g_scale[H_DIM];
__device__ float g_shift[H_DIM];
__device__ float g_conf[NP];               // attention logits

__device__ __forceinline__ void mma_bf16(float* c, const uint32_t* a, const uint32_t* b) {
    asm volatile("mma.sync.aligned.m16n8k16.row.col.f32.bf16.bf16.f32 "
                 "{%0,%1,%2,%3}, {%4,%5,%6,%7}, {%8,%9}, {%0,%1,%2,%3};"
                 : "+f"(c[0]), "+f"(c[1]), "+f"(c[2]), "+f"(c[3])
                 : "r"(a[0]), "r"(a[1]), "r"(a[2]), "r"(a[3]), "r"(b[0]), "r"(b[1]));
}
__device__ __forceinline__ void split_bf16(float v, __nv_bfloat16& h, __nv_bfloat16& l) {
    h = __float2bfloat16_rn(v);
    l = __float2bfloat16_rn(v - __bfloat162float(h));
}

// ---------------- validated HMMA bf16x3 GEMM (round-7 structure) ---------------
// Operand arrays selected INTERNALLY by EPI (device symbols, never host-passed):
// EPI 1: g_h = leakyrelu(cemb @ W1c + g_hi[nn]+g_hj[mm]+bias)   K=256
// EPI 0: outp = BN(h) @ W2 + bias                                K=1024
#define TK2   16
#define APAD2 24
template<int EPI>
__global__ __launch_bounds__(256)
void mma_gemm(const float* __restrict__ bias, float* __restrict__ outp)
{
    const __nv_bfloat16* __restrict__ Ahi = (EPI == 1) ? g_c_hi : g_hb_hi;
    const __nv_bfloat16* __restrict__ Alo = (EPI == 1) ? g_c_lo : g_hb_lo;
    const __nv_bfloat16* __restrict__ Bhi = (EPI == 1) ? g_W1t_hi : g_W2t_hi;
    const __nv_bfloat16* __restrict__ Blo = (EPI == 1) ? g_W1t_lo : g_W2t_lo;
    float* __restrict__ dst = (EPI == 1) ? g_h : outp;
    constexpr int K = (EPI == 1) ? C_EMB : H_DIM;
    constexpr int NC = K / TK2;

    __shared__ __align__(16) __nv_bfloat16 sAhi[2][128][APAD2];
    __shared__ __align__(16) __nv_bfloat16 sAlo[2][128][APAD2];
    __shared__ __align__(16) __nv_bfloat16 sBhi[2][128][APAD2];
    __shared__ __align__(16) __nv_bfloat16 sBlo[2][128][APAD2];

    const int tid = threadIdx.x;
    const int lane = tid & 31, wid = tid >> 5;
    const int m0 = blockIdx.y * 128, n0 = blockIdx.x * 128;

    const int m_base = (wid >> 2) * 64;
    const int n_base = (wid & 3) * 32;
    const int fr = lane >> 2;             // fragment row 0..7
    const int fk = (lane & 3) * 2;        // fragment k 0,2,4,6

    const int ld_row = tid >> 1, ld_c = (tid & 1) * 8;

    float acc[4][4][4];
#pragma unroll
    for (int i = 0; i < 4; i++)
#pragma unroll
        for (int j = 0; j < 4; j++)
#pragma unroll
            for (int r = 0; r < 4; r++) acc[i][j][r] = 0.f;

    // preload chunk 0 into buffer 0
    {
        const size_t ka = (size_t)(m0 + ld_row) * K + ld_c;
        const size_t kb = (size_t)(n0 + ld_row) * K + ld_c;
        *(uint4*)&sAhi[0][ld_row][ld_c] = *(const uint4*)(Ahi + ka);
        *(uint4*)&sAlo[0][ld_row][ld_c] = *(const uint4*)(Alo + ka);
        *(uint4*)&sBhi[0][ld_row][ld_c] = *(const uint4*)(Bhi + kb);
        *(uint4*)&sBlo[0][ld_row][ld_c] = *(const uint4*)(Blo + kb);
    }
    __syncthreads();

    for (int c = 0; c < NC; c++) {
        const int cur = c & 1, nxt = cur ^ 1;
        uint4 pa, pb, pc, pd;
        if (c + 1 < NC) {
            const size_t ka = (size_t)(m0 + ld_row) * K + (c + 1) * TK2 + ld_c;
            const size_t kb = (size_t)(n0 + ld_row) * K + (c + 1) * TK2 + ld_c;
            pa = *(const uint4*)(Ahi + ka);
            pb = *(const uint4*)(Alo + ka);
            pc = *(const uint4*)(Bhi + kb);
            pd = *(const uint4*)(Blo + kb);
        }

        uint32_t a_hi[4][4], a_lo[4][4], b_hi[4][2], b_lo[4][2];
#pragma unroll
        for (int mt = 0; mt < 4; mt++) {
            const int r0 = m_base + mt * 16 + fr;
            a_hi[mt][0] = *(const uint32_t*)&sAhi[cur][r0    ][fk];
            a_hi[mt][1] = *(const uint32_t*)&sAhi[cur][r0 + 8][fk];
            a_hi[mt][2] = *(const uint32_t*)&sAhi[cur][r0    ][fk + 8];
            a_hi[mt][3] = *(const uint32_t*)&sAhi[cur][r0 + 8][fk + 8];
            a_lo[mt][0] = *(const uint32_t*)&sAlo[cur][r0    ][fk];
            a_lo[mt][1] = *(const uint32_t*)&sAlo[cur][r0 + 8][fk];
            a_lo[mt][2] = *(const uint32_t*)&sAlo[cur][r0    ][fk + 8];
            a_lo[mt][3] = *(const uint32_t*)&sAlo[cur][r0 + 8][fk + 8];
        }
#pragma unroll
        for (int nt = 0; nt < 4; nt++) {
            const int n = n_base + nt * 8 + fr;
            b_hi[nt][0] = *(const uint32_t*)&sBhi[cur][n][fk];
            b_hi[nt][1] = *(const uint32_t*)&sBhi[cur][n][fk + 8];
            b_lo[nt][0] = *(const uint32_t*)&sBlo[cur][n][fk];
            b_lo[nt][1] = *(const uint32_t*)&sBlo[cur][n][fk + 8];
        }
#pragma unroll
        for (int mt = 0; mt < 4; mt++)
#pragma unroll
            for (int nt = 0; nt < 4; nt++) {
                mma_bf16(acc[mt][nt], a_hi[mt], b_hi[nt]);
                mma_bf16(acc[mt][nt], a_hi[mt], b_lo[nt]);
                mma_bf16(acc[mt][nt], a_lo[mt], b_hi[nt]);
            }

        if (c + 1 < NC) {
            *(uint4*)&sAhi[nxt][ld_row][ld_c] = pa;
            *(uint4*)&sAlo[nxt][ld_row][ld_c] = pb;
            *(uint4*)&sBhi[nxt][ld_row][ld_c] = pc;
            *(uint4*)&sBlo[nxt][ld_row][ld_c] = pd;
        }
        __syncthreads();
    }

    // epilogue: c0,c1 -> row fr; c2,c3 -> row fr+8
#pragma unroll
    for (int mt = 0; mt < 4; mt++)
#pragma unroll
        for (int nt = 0; nt < 4; nt++) {
            const int col0 = n0 + n_base + nt * 8 + fk;
#pragma unroll
            for (int half = 0; half < 2; half++) {
                const int row = m0 + m_base + mt * 16 + fr + half * 8;
                float v0 = acc[mt][nt][half * 2]     + bias[col0];
                float v1 = acc[mt][nt][half * 2 + 1] + bias[col0 + 1];
                if (EPI == 1) {
                    const int nn = row >> 8, mm = row & 255;
                    v0 += g_hi[nn * H_DIM + col0]     + g_hj[mm * H_DIM + col0];
                    v1 += g_hi[nn * H_DIM + col0 + 1] + g_hj[mm * H_DIM + col0 + 1];
                    v0 = (v0 >= 0.f) ? v0 : SLOPE * v0;
                    v1 = (v1 >= 0.f) ? v1 : SLOPE * v1;
                }
                *(float2*)(dst + (size_t)row * O_DIM + col0) = make_float2(v0, v1);
            }
        }
}

// ---------------- round-1 verbatim: small SIMT GEMM for hi/hj ------------------
__launch_bounds__(256)
__global__ void gemm_small(const float* __restrict__ A, const float* __restrict__ B,
                           int which)
{
    float* C = which ? g_hj : g_hi;
    __shared__ float As[8][132];
    __shared__ float Bs[8][128];
    const int tid = threadIdx.x;
    const int tx = tid & 15, ty = tid >> 4;
    const int m0 = blockIdx.y * 128, n0 = blockIdx.x * 128;
    float acc[8][8];
#pragma unroll
    for (int i = 0; i < 8; i++)
#pragma unroll
        for (int j = 0; j < 8; j++) acc[i][j] = 0.f;
    const int ar = tid >> 1, ak = (tid & 1) * 4;
    const int bk = tid >> 5, bc = (tid & 31) * 4;
    const float* Aptr = A + (size_t)(m0 + ar) * 1024 + ak;
    const float* Bptr = B + (size_t)bk * 1024 + n0 + bc;
    for (int k0 = 0; k0 < 1024; k0 += 8) {
        float4 av = *(const float4*)(Aptr + k0);
        float4 bv = *(const float4*)(Bptr + (size_t)k0 * 1024);
        As[ak][ar] = av.x; As[ak + 1][ar] = av.y; As[ak + 2][ar] = av.z; As[ak + 3][ar] = av.w;
        *(float4*)(&Bs[bk][bc]) = bv;
        __syncthreads();
#pragma unroll
        for (int kk = 0; kk < 8; kk++) {
            float a[8], b[8];
#pragma unroll
            for (int i = 0; i < 8; i++) a[i] = As[kk][ty * 8 + i];
#pragma unroll
            for (int j = 0; j < 8; j++) b[j] = Bs[kk][tx * 8 + j];
#pragma unroll
            for (int i = 0; i < 8; i++)
#pragma unroll
                for (int j = 0; j < 8; j++) acc[i][j] += a[i] * b[j];
        }
        __syncthreads();
    }
#pragma unroll
    for (int i = 0; i < 8; i++)
#pragma unroll
        for (int j = 0; j < 8; j++)
            C[(size_t)(m0 + ty * 8 + i) * 1024 + n0 + tx * 8 + j] = acc[i][j];
}

// ---------------- converters ---------------------------------------------------
__global__ void convert_cemb(const float* __restrict__ in)   // [NP*C_EMB] -> planes
{
    const size_t i = ((size_t)blockIdx.x * 256 + threadIdx.x) * 4;
    if (i >= (size_t)NP * C_EMB) return;
    const float4 v4 = *(const float4*)(in + i);
    const float v[4] = { v4.x, v4.y, v4.z, v4.w };
    uint32_t hw[2], lw[2];
#pragma unroll
    for (int p = 0; p < 2; p++) {
        __nv_bfloat16 h0, l0, h1, l1;
        split_bf16(v[2 * p], h0, l0);
        split_bf16(v[2 * p + 1], h1, l1);
        hw[p] = (uint32_t)__bfloat16_as_ushort(h0) | ((uint32_t)__bfloat16_as_ushort(h1) << 16);
        lw[p] = (uint32_t)__bfloat16_as_ushort(l0) | ((uint32_t)__bfloat16_as_ushort(l1) << 16);
    }
    *(uint2*)((char*)g_c_hi + i * 2) = make_uint2(hw[0], hw[1]);
    *(uint2*)((char*)g_c_lo + i * 2) = make_uint2(lw[0], lw[1]);
}

__global__ void split_W1t(const float* __restrict__ W1)   // W1c^T [j][k]
{
    const int j = blockIdx.x;            // 0..1023
    const int k = threadIdx.x;           // 0..255
    __nv_bfloat16 h, l;
    split_bf16(W1[(size_t)(2 * D_IN + k) * H_DIM + j], h, l);
    g_W1t_hi[j * C_EMB + k] = h;
    g_W1t_lo[j * C_EMB + k] = l;
}

__global__ void split_W2t(const float* __restrict__ W2)   // W2^T [j][k]
{
    const int j = blockIdx.x;
#pragma unroll
    for (int it = 0; it < 4; it++) {
        const int k = it * 256 + threadIdx.x;
        __nv_bfloat16 h, l;
        split_bf16(W2[(size_t)k * O_DIM + j], h, l);
        g_W2t_hi[(size_t)j * H_DIM + k] = h;
        g_W2t_lo[(size_t)j * H_DIM + k] = l;
    }
}

// ---------------- BN stats on fp32 g_h (validated round-7) ---------------------
__global__ void stats_f32()
{
    const int cp = blockIdx.x * 256 + threadIdx.x;
    const int rb = blockIdx.y;
    const int c0 = cp * 2;
    float s0 = 0.f, s1 = 0.f, q0 = 0.f, q1 = 0.f;
#pragma unroll 4
    for (int r = 0; r < 256; r++) {
        const float2 v = *(const float2*)&g_h[(size_t)(rb * 256 + r) * H_DIM + c0];
        s0 += v.x; q0 += v.x * v.x;
        s1 += v.y; q1 += v.y * v.y;
    }
    g_ps[rb * H_DIM + c0] = s0; g_ps[rb * H_DIM + c0 + 1] = s1;
    g_pq[rb * H_DIM + c0] = q0; g_pq[rb * H_DIM + c0 + 1] = q1;
}

__global__ void finalize_bn(const float* __restrict__ gamma, const float* __restrict__ beta)
{
    const int c = blockIdx.x * 256 + threadIdx.x;
    float s = 0.f, q = 0.f;
#pragma unroll
    for (int i = 0; i < RB_STATS; i++) { s += g_ps[i * H_DIM + c]; q += g_pq[i * H_DIM + c]; }
    const float inv = 1.0f / (float)NP;
    const float mean = s * inv;
    const float var = q * inv - mean * mean;
    const float sc = gamma[c] * rsqrtf(var + BN_EPS);
    g_scale[c] = sc;
    g_shift[c] = beta[c] - mean * sc;
}

// ---------------- BN-apply + split h -> bf16 planes (validated round-7) --------
__global__ void convert_h()
{
    const size_t i = ((size_t)blockIdx.x * 256 + threadIdx.x) * 4;
    if (i >= (size_t)NP * H_DIM) return;
    const int col = (int)(i & (H_DIM - 1));
    const float4 h4 = *(const float4*)&g_h[i];
    const float4 sc = *(const float4*)&g_scale[col];
    const float4 sh = *(const float4*)&g_shift[col];
    float v[4] = { h4.x * sc.x + sh.x, h4.y * sc.y + sh.y,
                   h4.z * sc.z + sh.z, h4.w * sc.w + sh.w };
    uint32_t hw[2], lw[2];
#pragma unroll
    for (int p = 0; p < 2; p++) {
        __nv_bfloat16 h0, l0, h1, l1;
        split_bf16(v[2 * p], h0, l0);
        split_bf16(v[2 * p + 1], h1, l1);
        hw[p] = (uint32_t)__bfloat16_as_ushort(h0) | ((uint32_t)__bfloat16_as_ushort(h1) << 16);
        lw[p] = (uint32_t)__bfloat16_as_ushort(l0) | ((uint32_t)__bfloat16_as_ushort(l1) << 16);
    }
    *(uint2*)((char*)g_hb_hi + i * 2) = make_uint2(hw[0], hw[1]);
    *(uint2*)((char*)g_hb_lo + i * 2) = make_uint2(lw[0], lw[1]);
}

// ---------------- attention: conf logits (1 warp per edge row) -----------------
__global__ void conf_kernel(const float* __restrict__ feat,
                            const float* __restrict__ w_att,
                            const float* __restrict__ b_att)
{
    __shared__ float ws[O_DIM];
    const int tid = threadIdx.x;
    const int warp = tid >> 5, lane = tid & 31;
    for (int i = tid; i < O_DIM; i += 256) ws[i] = w_att[i];
    __syncthreads();
    const int row = blockIdx.x * 8 + warp;
    const float* f = feat + (size_t)row * O_DIM;
    float s = 0.f;
    for (int i = lane; i < O_DIM; i += 32) s += f[i] * ws[i];
#pragma unroll
    for (int o = 16; o; o >>= 1) s += __shfl_xor_sync(0xFFFFFFFFu, s, o);
    if (lane == 0) g_conf[row] = s + b_att[0];
}

// ---------------- softmax + weighted aggregation -------------------------------
__global__ void attn_agg(const float* __restrict__ feat, float* __restrict__ enhanced)
{
    __shared__ float conf[N_OBJ];
    __shared__ float red[256];
    const int n = blockIdx.x, tid = threadIdx.x;
    const int c0 = blockIdx.y * 256;
    const float v = g_conf[n * N_OBJ + tid];
    red[tid] = v;
    __syncthreads();
    for (int o = 128; o; o >>= 1) {
        if (tid < o) red[tid] = fmaxf(red[tid], red[tid + o]);
        __syncthreads();
    }
    const float mx = red[0];
    __syncthreads();
    const float e = expf(v - mx);
    red[tid] = e;
    __syncthreads();
    for (int o = 128; o; o >>= 1) {
        if (tid < o) red[tid] += red[tid + o];
        __syncthreads();
    }
    const float p = e / red[0];
    __syncthreads();
    conf[tid] = p;
    __syncthreads();

    float acc = 0.f;
    const float* base = feat + (size_t)n * N_OBJ * O_DIM + c0 + tid;
#pragma unroll 4
    for (int m = 0; m < N_OBJ; m++)
        acc += conf[m] * base[(size_t)m * O_DIM];
    enhanced[(size_t)n * O_DIM + c0 + tid] = acc;
}

// ---------------- round-7 verbatim: relation -----------------------------------
__launch_bounds__(256)
__global__ void relation_kernel(const float* __restrict__ feat,
                                const float* __restrict__ Wrel,
                                const float* __restrict__ brel,
                                float* __restrict__ out)
{
    __shared__ float As[128][65];
    __shared__ float Bs[64][52];

    const int tid = threadIdx.x;
    const int cg = tid & 3;
    const int rh = tid >> 2;
    const int r0 = rh * 2, r1 = r0 + 1;
    const int row0 = blockIdx.x * 128;
    const int c0 = cg * 13;

    float acc0[13], acc1[13];
#pragma unroll
    for (int j = 0; j < 13; j++) { acc0[j] = 0.f; acc1[j] = 0.f; }

    for (int kb = 0; kb < O_DIM; kb += 64) {
#pragma unroll
        for (int i = 0; i < 8; i++) {
            const int f = tid + i * 256;
            const int r = f >> 4;
            const int kk = (f & 15) * 4;
            float4 v = *(const float4*)(feat + (size_t)(row0 + r) * O_DIM + kb + kk);
            As[r][kk + 0] = v.x; As[r][kk + 1] = v.y; As[r][kk + 2] = v.z; As[r][kk + 3] = v.w;
        }
        for (int i = tid; i < 64 * R_DIM; i += 256) {
            const int k = i / R_DIM, c = i % R_DIM;
            Bs[k][c] = Wrel[(size_t)(kb + k) * R_DIM + c];
        }
        __syncthreads();
#pragma unroll 4
        for (int k = 0; k < 64; k++) {
            const float a0 = As[r0][k], a1 = As[r1][k];
#pragma unroll
            for (int j = 0; j < 13; j++) {
                const int c = c0 + j;
                if (c < R_DIM) {
                    const float b = Bs[k][c];
                    acc0[j] += a0 * b;
                    acc1[j] += a1 * b;
                }
            }
        }
        __syncthreads();
    }
#pragma unroll
    for (int j = 0; j < 13; j++) {
        const int c = c0 + j;
        if (c < R_DIM) {
            out[(size_t)(row0 + r0) * R_DIM + c] = acc0[j] + brel[c];
            out[(size_t)(row0 + r1) * R_DIM + c] = acc1[j] + brel[c];
        }
    }
}

// ---------------- launcher ------------------------------------------------------
// NOTE: every kernel argument below is a d_in/d_out pointer. Device scratch is
// reached only through device-code symbol references.
extern "C" void kernel_launch(void* const* d_in, const int* in_sizes, int n_in,
                              void* d_out, int out_size)
{
    const float* feats = (const float*)d_in[0];
    const float* cemb  = (const float*)d_in[1];
    const float* W1    = (const float*)d_in[2];
    const float* b1    = (const float*)d_in[3];
    const float* gamma = (const float*)d_in[4];
    const float* beta  = (const float*)d_in[5];
    const float* W2    = (const float*)d_in[6];
    const float* b2    = (const float*)d_in[7];
    const float* watt  = (const float*)d_in[8];
    const float* batt  = (const float*)d_in[9];
    const float* Wrel  = (const float*)d_in[10];
    const float* brel  = (const float*)d_in[11];

    float* out      = (float*)d_out;
    float* feat     = out;
    float* enhanced = out + (size_t)NP * O_DIM;
    float* relation = enhanced + (size_t)N_OBJ * O_DIM;

    // converters (independent of GEMMs)
    convert_cemb<<<(int)(((size_t)NP * C_EMB / 4 + 255) / 256), 256>>>(cemb);
    split_W1t<<<H_DIM, 256>>>(W1);
    split_W2t<<<O_DIM, 256>>>(W2);

    // hi = feats @ W1[:D], hj = feats @ W1[D:2D]
    gemm_small<<<dim3(8, 2), 256>>>(feats, W1, 0);
    gemm_small<<<dim3(8, 2), 256>>>(feats, W1 + (size_t)D_IN * H_DIM, 1);

    // GEMM1 (HMMA): g_h = leakyrelu(cemb @ W1c + hi + hj + b1)
    mma_gemm<1><<<dim3(8, 512), 256>>>(b1, nullptr);

    // BN stats + fold into scale/shift
    stats_f32<<<dim3(2, RB_STATS), 256>>>();
    finalize_bn<<<4, 256>>>(gamma, beta);

    // BN-apply + split h
    convert_h<<<(int)(((size_t)NP * H_DIM / 4 + 255) / 256), 256>>>();

    // GEMM2 (HMMA): feat = BN(h) @ W2 + b2
    mma_gemm<0><<<dim3(8, 512), 256>>>(b2, feat);

    // attention: logits, then softmax+aggregate
    conf_kernel<<<NP / 8, 256>>>(feat, watt, batt);
    attn_agg<<<dim3(N_OBJ, 4), 256>>>(feat, enhanced);

    // relation classifier
    relation_kernel<<<NP / 128, 256>>>(feat, Wrel, brel, relation);
}

// round 10
// speedup vs baseline: 2.0793x; 1.1048x over previous
#include <cuda_runtime.h>
#include <cuda_bf16.h>
#include <cstdint>
#include <math.h>

#define N_OBJ 256
#define D_IN  1024
#define C_EMB 256
#define H_DIM 1024
#define O_DIM 1024
#define R_DIM 51
#define NP    (N_OBJ * N_OBJ)   /* 65536 edge rows */
#define BN_EPS 1e-5f
#define SLOPE  0.01f
#define RB_STATS 256

// ---------------- scratch (static device globals; no allocation) ---------------
// RULE (root cause of rounds 2-8): these symbols are ONLY referenced inside
// device code. NEVER passed as kernel arguments from kernel_launch (host code
// would pass the host shadow address; ATS on GB300 makes it read zeros).
__device__ __align__(128) __nv_bfloat16 g_c_hi[(size_t)NP * C_EMB];   // cemb split
__device__ __align__(128) __nv_bfloat16 g_c_lo[(size_t)NP * C_EMB];
__device__ __align__(128) __nv_bfloat16 g_W1t_hi[H_DIM * C_EMB];      // W1c^T split [j][k]
__device__ __align__(128) __nv_bfloat16 g_W1t_lo[H_DIM * C_EMB];
__device__ __align__(128) __nv_bfloat16 g_hb_hi[(size_t)NP * H_DIM];  // h split (pre-BN)
__device__ __align__(128) __nv_bfloat16 g_hb_lo[(size_t)NP * H_DIM];
__device__ __align__(128) __nv_bfloat16 g_W2t_hi[O_DIM * H_DIM];      // (scale.W2)^T split
__device__ __align__(128) __nv_bfloat16 g_W2t_lo[O_DIM * H_DIM];
__device__ float g_hi[N_OBJ * H_DIM];
__device__ float g_hj[N_OBJ * H_DIM];
__device__ float g_part[8 * N_OBJ * H_DIM];   // K-split partials for hi/hj
__device__ float g_ps[RB_STATS * H_DIM];
__device__ float g_pq[RB_STATS * H_DIM];
__device__ float g_scale[H_DIM];
__device__ float g_shift[H_DIM];
__device__ float g_bias2[O_DIM];              // b2 + shift . W2
__device__ float g_conf[NP];                  // attention logits

__device__ __forceinline__ void mma_bf16(float* c, const uint32_t* a, const uint32_t* b) {
    asm volatile("mma.sync.aligned.m16n8k16.row.col.f32.bf16.bf16.f32 "
                 "{%0,%1,%2,%3}, {%4,%5,%6,%7}, {%8,%9}, {%0,%1,%2,%3};"
                 : "+f"(c[0]), "+f"(c[1]), "+f"(c[2]), "+f"(c[3])
                 : "r"(a[0]), "r"(a[1]), "r"(a[2]), "r"(a[3]), "r"(b[0]), "r"(b[1]));
}
__device__ __forceinline__ void split_bf16(float v, __nv_bfloat16& h, __nv_bfloat16& l) {
    h = __float2bfloat16_rn(v);
    l = __float2bfloat16_rn(v - __bfloat162float(h));
}

// ---------------- validated HMMA bf16x3 GEMM (round-9 structure) ---------------
// Operand arrays selected INTERNALLY by EPI (device symbols, never host-passed):
// EPI 1: h = leakyrelu(cemb @ W1c + g_hi[nn]+g_hj[mm]+bias) -> split planes  K=256
// EPI 0: outp(feat) = h @ (scale.W2) + g_bias2                               K=1024
#define TK2   16
#define APAD2 24
template<int EPI>
__global__ __launch_bounds__(256)
void mma_gemm(const float* __restrict__ bias, float* __restrict__ outp)
{
    const __nv_bfloat16* __restrict__ Ahi = (EPI == 1) ? g_c_hi : g_hb_hi;
    const __nv_bfloat16* __restrict__ Alo = (EPI == 1) ? g_c_lo : g_hb_lo;
    const __nv_bfloat16* __restrict__ Bhi = (EPI == 1) ? g_W1t_hi : g_W2t_hi;
    const __nv_bfloat16* __restrict__ Blo = (EPI == 1) ? g_W1t_lo : g_W2t_lo;
    constexpr int K = (EPI == 1) ? C_EMB : H_DIM;
    constexpr int NC = K / TK2;

    __shared__ __align__(16) __nv_bfloat16 sAhi[2][128][APAD2];
    __shared__ __align__(16) __nv_bfloat16 sAlo[2][128][APAD2];
    __shared__ __align__(16) __nv_bfloat16 sBhi[2][128][APAD2];
    __shared__ __align__(16) __nv_bfloat16 sBlo[2][128][APAD2];

    const int tid = threadIdx.x;
    const int lane = tid & 31, wid = tid >> 5;
    const int m0 = blockIdx.y * 128, n0 = blockIdx.x * 128;

    const int m_base = (wid >> 2) * 64;
    const int n_base = (wid & 3) * 32;
    const int fr = lane >> 2;             // fragment row 0..7
    const int fk = (lane & 3) * 2;        // fragment k 0,2,4,6

    const int ld_row = tid >> 1, ld_c = (tid & 1) * 8;

    float acc[4][4][4];
#pragma unroll
    for (int i = 0; i < 4; i++)
#pragma unroll
        for (int j = 0; j < 4; j++)
#pragma unroll
            for (int r = 0; r < 4; r++) acc[i][j][r] = 0.f;

    // preload chunk 0 into buffer 0
    {
        const size_t ka = (size_t)(m0 + ld_row) * K + ld_c;
        const size_t kb = (size_t)(n0 + ld_row) * K + ld_c;
        *(uint4*)&sAhi[0][ld_row][ld_c] = *(const uint4*)(Ahi + ka);
        *(uint4*)&sAlo[0][ld_row][ld_c] = *(const uint4*)(Alo + ka);
        *(uint4*)&sBhi[0][ld_row][ld_c] = *(const uint4*)(Bhi + kb);
        *(uint4*)&sBlo[0][ld_row][ld_c] = *(const uint4*)(Blo + kb);
    }
    __syncthreads();

    for (int c = 0; c < NC; c++) {
        const int cur = c & 1, nxt = cur ^ 1;
        uint4 pa, pb, pc, pd;
        if (c + 1 < NC) {
            const size_t ka = (size_t)(m0 + ld_row) * K + (c + 1) * TK2 + ld_c;
            const size_t kb = (size_t)(n0 + ld_row) * K + (c + 1) * TK2 + ld_c;
            pa = *(const uint4*)(Ahi + ka);
            pb = *(const uint4*)(Alo + ka);
            pc = *(const uint4*)(Bhi + kb);
            pd = *(const uint4*)(Blo + kb);
        }

        uint32_t a_hi[4][4], a_lo[4][4], b_hi[4][2], b_lo[4][2];
#pragma unroll
        for (int mt = 0; mt < 4; mt++) {
            const int r0 = m_base + mt * 16 + fr;
            a_hi[mt][0] = *(const uint32_t*)&sAhi[cur][r0    ][fk];
            a_hi[mt][1] = *(const uint32_t*)&sAhi[cur][r0 + 8][fk];
            a_hi[mt][2] = *(const uint32_t*)&sAhi[cur][r0    ][fk + 8];
            a_hi[mt][3] = *(const uint32_t*)&sAhi[cur][r0 + 8][fk + 8];
            a_lo[mt][0] = *(const uint32_t*)&sAlo[cur][r0    ][fk];
            a_lo[mt][1] = *(const uint32_t*)&sAlo[cur][r0 + 8][fk];
            a_lo[mt][2] = *(const uint32_t*)&sAlo[cur][r0    ][fk + 8];
            a_lo[mt][3] = *(const uint32_t*)&sAlo[cur][r0 + 8][fk + 8];
        }
#pragma unroll
        for (int nt = 0; nt < 4; nt++) {
            const int n = n_base + nt * 8 + fr;
            b_hi[nt][0] = *(const uint32_t*)&sBhi[cur][n][fk];
            b_hi[nt][1] = *(const uint32_t*)&sBhi[cur][n][fk + 8];
            b_lo[nt][0] = *(const uint32_t*)&sBlo[cur][n][fk];
            b_lo[nt][1] = *(const uint32_t*)&sBlo[cur][n][fk + 8];
        }
#pragma unroll
        for (int mt = 0; mt < 4; mt++)
#pragma unroll
            for (int nt = 0; nt < 4; nt++) {
                mma_bf16(acc[mt][nt], a_hi[mt], b_hi[nt]);
                mma_bf16(acc[mt][nt], a_hi[mt], b_lo[nt]);
                mma_bf16(acc[mt][nt], a_lo[mt], b_hi[nt]);
            }

        if (c + 1 < NC) {
            *(uint4*)&sAhi[nxt][ld_row][ld_c] = pa;
            *(uint4*)&sAlo[nxt][ld_row][ld_c] = pb;
            *(uint4*)&sBhi[nxt][ld_row][ld_c] = pc;
            *(uint4*)&sBlo[nxt][ld_row][ld_c] = pd;
        }
        __syncthreads();
    }

    // epilogue: c0,c1 -> row fr; c2,c3 -> row fr+8
#pragma unroll
    for (int mt = 0; mt < 4; mt++)
#pragma unroll
        for (int nt = 0; nt < 4; nt++) {
            const int col0 = n0 + n_base + nt * 8 + fk;
#pragma unroll
            for (int half = 0; half < 2; half++) {
                const int row = m0 + m_base + mt * 16 + fr + half * 8;
                float v0 = acc[mt][nt][half * 2];
                float v1 = acc[mt][nt][half * 2 + 1];
                if (EPI == 1) {
                    const int nn = row >> 8, mm = row & 255;
                    v0 += g_hi[nn * H_DIM + col0]     + g_hj[mm * H_DIM + col0]     + bias[col0];
                    v1 += g_hi[nn * H_DIM + col0 + 1] + g_hj[mm * H_DIM + col0 + 1] + bias[col0 + 1];
                    v0 = (v0 >= 0.f) ? v0 : SLOPE * v0;
                    v1 = (v1 >= 0.f) ? v1 : SLOPE * v1;
                    __nv_bfloat16 h0, l0, h1, l1;
                    split_bf16(v0, h0, l0);
                    split_bf16(v1, h1, l1);
                    const size_t o = (size_t)row * H_DIM + col0;
                    *(__nv_bfloat162*)(g_hb_hi + o) = __nv_bfloat162(h0, h1);
                    *(__nv_bfloat162*)(g_hb_lo + o) = __nv_bfloat162(l0, l1);
                } else {
                    v0 += g_bias2[col0];
                    v1 += g_bias2[col0 + 1];
                    *(float2*)(outp + (size_t)row * O_DIM + col0) = make_float2(v0, v1);
                }
            }
        }
}

// ---------------- hi/hj: K-split fp32 GEMM (128 blocks) + reduce ---------------
// z = which*4 + kc : which selects W1[:D] vs W1[D:2D], kc = K chunk of 256
__launch_bounds__(256)
__global__ void gemm_hij(const float* __restrict__ feats, const float* __restrict__ W1)
{
    const int which = blockIdx.z >> 2;
    const int kc = blockIdx.z & 3;
    __shared__ float As[8][132];
    __shared__ float Bs[8][128];
    const int tid = threadIdx.x;
    const int tx = tid & 15, ty = tid >> 4;
    const int m0 = blockIdx.y * 128, n0 = blockIdx.x * 128;
    float acc[8][8];
#pragma unroll
    for (int i = 0; i < 8; i++)
#pragma unroll
        for (int j = 0; j < 8; j++) acc[i][j] = 0.f;
    const int ar = tid >> 1, ak = (tid & 1) * 4;
    const int bk = tid >> 5, bc = (tid & 31) * 4;
    const float* Aptr = feats + (size_t)(m0 + ar) * 1024 + kc * 256 + ak;
    const float* Bptr = W1 + (size_t)(which * D_IN + kc * 256 + bk) * 1024 + n0 + bc;
    for (int k0 = 0; k0 < 256; k0 += 8) {
        float4 av = *(const float4*)(Aptr + k0);
        float4 bv = *(const float4*)(Bptr + (size_t)k0 * 1024);
        As[ak][ar] = av.x; As[ak + 1][ar] = av.y; As[ak + 2][ar] = av.z; As[ak + 3][ar] = av.w;
        *(float4*)(&Bs[bk][bc]) = bv;
        __syncthreads();
#pragma unroll
        for (int kk = 0; kk < 8; kk++) {
            float a[8], b[8];
#pragma unroll
            for (int i = 0; i < 8; i++) a[i] = As[kk][ty * 8 + i];
#pragma unroll
            for (int j = 0; j < 8; j++) b[j] = Bs[kk][tx * 8 + j];
#pragma unroll
            for (int i = 0; i < 8; i++)
#pragma unroll
                for (int j = 0; j < 8; j++) acc[i][j] += a[i] * b[j];
        }
        __syncthreads();
    }
    float* dst = g_part + (size_t)blockIdx.z * N_OBJ * H_DIM;
#pragma unroll
    for (int i = 0; i < 8; i++)
#pragma unroll
        for (int j = 0; j < 8; j++)
            dst[(size_t)(m0 + ty * 8 + i) * 1024 + n0 + tx * 8 + j] = acc[i][j];
}

__global__ void reduce_hij()
{
    const int idx = blockIdx.x * 256 + threadIdx.x;         // 0 .. 512K-1
    const int which = idx >> 18;                            // 0: hi, 1: hj
    const int base = idx & (N_OBJ * H_DIM - 1);
    const size_t stride = (size_t)N_OBJ * H_DIM;
    const float* p = g_part + (size_t)which * 4 * stride + base;
    const float s = p[0] + p[stride] + p[2 * stride] + p[3 * stride];
    if (which == 0) g_hi[base] = s;
    else            g_hj[base] = s;
}

// ---------------- converters ---------------------------------------------------
__global__ void convert_cemb(const float* __restrict__ in)   // [NP*C_EMB] -> planes
{
    const size_t i = ((size_t)blockIdx.x * 256 + threadIdx.x) * 4;
    if (i >= (size_t)NP * C_EMB) return;
    const float4 v4 = *(const float4*)(in + i);
    const float v[4] = { v4.x, v4.y, v4.z, v4.w };
    uint32_t hw[2], lw[2];
#pragma unroll
    for (int p = 0; p < 2; p++) {
        __nv_bfloat16 h0, l0, h1, l1;
        split_bf16(v[2 * p], h0, l0);
        split_bf16(v[2 * p + 1], h1, l1);
        hw[p] = (uint32_t)__bfloat16_as_ushort(h0) | ((uint32_t)__bfloat16_as_ushort(h1) << 16);
        lw[p] = (uint32_t)__bfloat16_as_ushort(l0) | ((uint32_t)__bfloat16_as_ushort(l1) << 16);
    }
    *(uint2*)((char*)g_c_hi + i * 2) = make_uint2(hw[0], hw[1]);
    *(uint2*)((char*)g_c_lo + i * 2) = make_uint2(lw[0], lw[1]);
}

// W1c^T split via 32x32 tiled transpose. grid (C_EMB/32, H_DIM/32), 256 thr.
__global__ void split_W1t(const float* __restrict__ W1)
{
    __shared__ float t[32][33];
    const int kb = blockIdx.x * 32;     // k base (0..255)
    const int jb = blockIdx.y * 32;     // j base (0..1023)
    const int tx = threadIdx.x & 31, ty = threadIdx.x >> 5;   // 32 x 8
#pragma unroll
    for (int r = 0; r < 4; r++) {
        const int k = kb + ty + r * 8;
        t[ty + r * 8][tx] = W1[(size_t)(2 * D_IN + k) * H_DIM + jb + tx];
    }
    __syncthreads();
#pragma unroll
    for (int r = 0; r < 4; r++) {
        const int j = jb + ty + r * 8;
        const int k = kb + tx;
        __nv_bfloat16 h, l;
        split_bf16(t[tx][ty + r * 8], h, l);
        g_W1t_hi[(size_t)j * C_EMB + k] = h;
        g_W1t_lo[(size_t)j * C_EMB + k] = l;
    }
}

// (scale.W2)^T split via 32x32 tiled transpose. grid (H_DIM/32, O_DIM/32).
__global__ void build_W2ts(const float* __restrict__ W2)
{
    __shared__ float t[32][33];
    const int kb = blockIdx.x * 32;     // k base
    const int jb = blockIdx.y * 32;     // j base
    const int tx = threadIdx.x & 31, ty = threadIdx.x >> 5;
#pragma unroll
    for (int r = 0; r < 4; r++) {
        const int k = kb + ty + r * 8;
        t[ty + r * 8][tx] = W2[(size_t)k * O_DIM + jb + tx];
    }
    __syncthreads();
#pragma unroll
    for (int r = 0; r < 4; r++) {
        const int j = jb + ty + r * 8;
        const int k = kb + tx;
        __nv_bfloat16 h, l;
        split_bf16(g_scale[k] * t[tx][ty + r * 8], h, l);
        g_W2t_hi[(size_t)j * H_DIM + k] = h;
        g_W2t_lo[(size_t)j * H_DIM + k] = l;
    }
}

// bias2[j] = b2[j] + sum_k shift[k] * W2[k][j]
__global__ void build_bias2(const float* __restrict__ W2, const float* __restrict__ b2)
{
    const int j = blockIdx.x * 256 + threadIdx.x;
    float s = b2[j];
#pragma unroll 4
    for (int k = 0; k < H_DIM; k++)
        s += g_shift[k] * W2[(size_t)k * O_DIM + j];
    g_bias2[j] = s;
}

// ---------------- BN stats from split planes (deterministic) -------------------
__global__ void stats_planes()
{
    const int cp = blockIdx.x * 256 + threadIdx.x;
    const int rb = blockIdx.y;
    const int c0 = cp * 2;
    float s0 = 0.f, s1 = 0.f, q0 = 0.f, q1 = 0.f;
#pragma unroll 4
    for (int r = 0; r < 256; r++) {
        const size_t o = (size_t)(rb * 256 + r) * H_DIM + c0;
        const __nv_bfloat162 h2 = *(const __nv_bfloat162*)(g_hb_hi + o);
        const __nv_bfloat162 l2 = *(const __nv_bfloat162*)(g_hb_lo + o);
        const float v0 = __bfloat162float(h2.x) + __bfloat162float(l2.x);
        const float v1 = __bfloat162float(h2.y) + __bfloat162float(l2.y);
        s0 += v0; q0 += v0 * v0;
        s1 += v1; q1 += v1 * v1;
    }
    g_ps[rb * H_DIM + c0] = s0; g_ps[rb * H_DIM + c0 + 1] = s1;
    g_pq[rb * H_DIM + c0] = q0; g_pq[rb * H_DIM + c0 + 1] = q1;
}

__global__ void finalize_bn(const float* __restrict__ gamma, const float* __restrict__ beta)
{
    const int c = blockIdx.x * 256 + threadIdx.x;
    float s = 0.f, q = 0.f;
#pragma unroll
    for (int i = 0; i < RB_STATS; i++) { s += g_ps[i * H_DIM + c]; q += g_pq[i * H_DIM + c]; }
    const float inv = 1.0f / (float)NP;
    const float mean = s * inv;
    const float var = q * inv - mean * mean;
    const float sc = gamma[c] * rsqrtf(var + BN_EPS);
    g_scale[c] = sc;
    g_shift[c] = beta[c] - mean * sc;
}

// ---------------- attention: conf logits (1 warp per edge row) -----------------
__global__ void conf_kernel(const float* __restrict__ feat,
                            const float* __restrict__ w_att,
                            const float* __restrict__ b_att)
{
    __shared__ float ws[O_DIM];
    const int tid = threadIdx.x;
    const int warp = tid >> 5, lane = tid & 31;
    for (int i = tid; i < O_DIM; i += 256) ws[i] = w_att[i];
    __syncthreads();
    const int row = blockIdx.x * 8 + warp;
    const float* f = feat + (size_t)row * O_DIM;
    float s = 0.f;
    for (int i = lane; i < O_DIM; i += 32) s += f[i] * ws[i];
#pragma unroll
    for (int o = 16; o; o >>= 1) s += __shfl_xor_sync(0xFFFFFFFFu, s, o);
    if (lane == 0) g_conf[row] = s + b_att[0];
}

// ---------------- softmax + weighted aggregation -------------------------------
__global__ void attn_agg(const float* __restrict__ feat, float* __restrict__ enhanced)
{
    __shared__ float conf[N_OBJ];
    __shared__ float red[256];
    const int n = blockIdx.x, tid = threadIdx.x;
    const int c0 = blockIdx.y * 256;
    const float v = g_conf[n * N_OBJ + tid];
    red[tid] = v;
    __syncthreads();
    for (int o = 128; o; o >>= 1) {
        if (tid < o) red[tid] = fmaxf(red[tid], red[tid + o]);
        __syncthreads();
    }
    const float mx = red[0];
    __syncthreads();
    const float e = expf(v - mx);
    red[tid] = e;
    __syncthreads();
    for (int o = 128; o; o >>= 1) {
        if (tid < o) red[tid] += red[tid + o];
        __syncthreads();
    }
    const float p = e / red[0];
    __syncthreads();
    conf[tid] = p;
    __syncthreads();

    float acc = 0.f;
    const float* base = feat + (size_t)n * N_OBJ * O_DIM + c0 + tid;
#pragma unroll 4
    for (int m = 0; m < N_OBJ; m++)
        acc += conf[m] * base[(size_t)m * O_DIM];
    enhanced[(size_t)n * O_DIM + c0 + tid] = acc;
}

// ---------------- round-7 verbatim: relation -----------------------------------
__launch_bounds__(256)
__global__ void relation_kernel(const float* __restrict__ feat,
                                const float* __restrict__ Wrel,
                                const float* __restrict__ brel,
                                float* __restrict__ out)
{
    __shared__ float As[128][65];
    __shared__ float Bs[64][52];

    const int tid = threadIdx.x;
    const int cg = tid & 3;
    const int rh = tid >> 2;
    const int r0 = rh * 2, r1 = r0 + 1;
    const int row0 = blockIdx.x * 128;
    const int c0 = cg * 13;

    float acc0[13], acc1[13];
#pragma unroll
    for (int j = 0; j < 13; j++) { acc0[j] = 0.f; acc1[j] = 0.f; }

    for (int kb = 0; kb < O_DIM; kb += 64) {
#pragma unroll
        for (int i = 0; i < 8; i++) {
            const int f = tid + i * 256;
            const int r = f >> 4;
            const int kk = (f & 15) * 4;
            float4 v = *(const float4*)(feat + (size_t)(row0 + r) * O_DIM + kb + kk);
            As[r][kk + 0] = v.x; As[r][kk + 1] = v.y; As[r][kk + 2] = v.z; As[r][kk + 3] = v.w;
        }
        for (int i = tid; i < 64 * R_DIM; i += 256) {
            const int k = i / R_DIM, c = i % R_DIM;
            Bs[k][c] = Wrel[(size_t)(kb + k) * R_DIM + c];
        }
        __syncthreads();
#pragma unroll 4
        for (int k = 0; k < 64; k++) {
            const float a0 = As[r0][k], a1 = As[r1][k];
#pragma unroll
            for (int j = 0; j < 13; j++) {
                const int c = c0 + j;
                if (c < R_DIM) {
                    const float b = Bs[k][c];
                    acc0[j] += a0 * b;
                    acc1[j] += a1 * b;
                }
            }
        }
        __syncthreads();
    }
#pragma unroll
    for (int j = 0; j < 13; j++) {
        const int c = c0 + j;
        if (c < R_DIM) {
            out[(size_t)(row0 + r0) * R_DIM + c] = acc0[j] + brel[c];
            out[(size_t)(row0 + r1) * R_DIM + c] = acc1[j] + brel[c];
        }
    }
}

// ---------------- launcher ------------------------------------------------------
// NOTE: every kernel argument below is a d_in/d_out pointer. Device scratch is
// reached only through device-code symbol references.
extern "C" void kernel_launch(void* const* d_in, const int* in_sizes, int n_in,
                              void* d_out, int out_size)
{
    const float* feats = (const float*)d_in[0];
    const float* cemb  = (const float*)d_in[1];
    const float* W1    = (const float*)d_in[2];
    const float* b1    = (const float*)d_in[3];
    const float* gamma = (const float*)d_in[4];
    const float* beta  = (const float*)d_in[5];
    const float* W2    = (const float*)d_in[6];
    const float* b2    = (const float*)d_in[7];
    const float* watt  = (const float*)d_in[8];
    const float* batt  = (const float*)d_in[9];
    const float* Wrel  = (const float*)d_in[10];
    const float* brel  = (const float*)d_in[11];

    float* out      = (float*)d_out;
    float* feat     = out;
    float* enhanced = out + (size_t)NP * O_DIM;
    float* relation = enhanced + (size_t)N_OBJ * O_DIM;

    // converters (independent of GEMMs)
    convert_cemb<<<(int)(((size_t)NP * C_EMB / 4 + 255) / 256), 256>>>(cemb);
    split_W1t<<<dim3(C_EMB / 32, H_DIM / 32), 256>>>(W1);

    // hi/hj: K-split GEMM + deterministic reduce
    gemm_hij<<<dim3(8, 2, 8), 256>>>(feats, W1);
    reduce_hij<<<2 * N_OBJ * H_DIM / 256, 256>>>();

    // GEMM1 (HMMA): h = leakyrelu(cemb @ W1c + hi + hj + b1) -> split planes
    mma_gemm<1><<<dim3(8, 512), 256>>>(b1, nullptr);

    // BN stats + fold
    stats_planes<<<dim3(2, RB_STATS), 256>>>();
    finalize_bn<<<4, 256>>>(gamma, beta);
    build_W2ts<<<dim3(H_DIM / 32, O_DIM / 32), 256>>>(W2);
    build_bias2<<<O_DIM / 256, 256>>>(W2, b2);

    // GEMM2 (HMMA): feat = h @ (scale.W2) + bias2
    mma_gemm<0><<<dim3(8, 512), 256>>>(nullptr, feat);

    // attention: logits, then softmax+aggregate
    conf_kernel<<<NP / 8, 256>>>(feat, watt, batt);
    attn_agg<<<dim3(N_OBJ, 4), 256>>>(feat, enhanced);

    // relation classifier
    relation_kernel<<<NP / 128, 256>>>(feat, Wrel, brel, relation);
}

// round 11
// speedup vs baseline: 2.1706x; 1.0439x over previous
#include <cuda_runtime.h>
#include <cuda_bf16.h>
#include <cstdint>
#include <math.h>

#define N_OBJ 256
#define D_IN  1024
#define C_EMB 256
#define H_DIM 1024
#define O_DIM 1024
#define R_DIM 51
#define NP    (N_OBJ * N_OBJ)   /* 65536 edge rows */
#define BN_EPS 1e-5f
#define SLOPE  0.01f
#define RB_STATS 256
#define N2TOT 1152               /* 1024 feat + 51 rel + 1 conf + 76 pad */

// ---------------- scratch (static device globals; no allocation) ---------------
// RULE (root cause of rounds 2-8): these symbols are ONLY referenced inside
// device code. NEVER passed as kernel arguments from kernel_launch (host code
// would pass the host shadow address; ATS on GB300 makes it read zeros).
__device__ __align__(128) __nv_bfloat16 g_c_hi[(size_t)NP * C_EMB];   // cemb split
__device__ __align__(128) __nv_bfloat16 g_c_lo[(size_t)NP * C_EMB];
__device__ __align__(128) __nv_bfloat16 g_W1t_hi[H_DIM * C_EMB];      // W1c^T split [j][k]
__device__ __align__(128) __nv_bfloat16 g_W1t_lo[H_DIM * C_EMB];
__device__ __align__(128) __nv_bfloat16 g_hb_hi[(size_t)NP * H_DIM];  // h split (pre-BN)
__device__ __align__(128) __nv_bfloat16 g_hb_lo[(size_t)NP * H_DIM];
__device__ __align__(128) __nv_bfloat16 g_W2t_hi[(size_t)N2TOT * H_DIM]; // combined B^T split
__device__ __align__(128) __nv_bfloat16 g_W2t_lo[(size_t)N2TOT * H_DIM];
__device__ float g_hi[N_OBJ * H_DIM];
__device__ float g_hj[N_OBJ * H_DIM];
__device__ float g_part[8 * N_OBJ * H_DIM];   // K-split partials for hi/hj
__device__ float g_ps[RB_STATS * H_DIM];
__device__ float g_pq[RB_STATS * H_DIM];
__device__ float g_scale[H_DIM];
__device__ float g_shift[H_DIM];
__device__ float g_bias2[N2TOT];              // [b2+shift.W2 | rel bias | conf bias | 0]
__device__ float g_wrelc[H_DIM * R_DIM];      // W2 @ W_rel
__device__ float g_wattc[H_DIM];              // W2 @ w_att
__device__ float g_conf[NP];                  // attention logits

__device__ __forceinline__ void mma_bf16(float* c, const uint32_t* a, const uint32_t* b) {
    asm volatile("mma.sync.aligned.m16n8k16.row.col.f32.bf16.bf16.f32 "
                 "{%0,%1,%2,%3}, {%4,%5,%6,%7}, {%8,%9}, {%0,%1,%2,%3};"
                 : "+f"(c[0]), "+f"(c[1]), "+f"(c[2]), "+f"(c[3])
                 : "r"(a[0]), "r"(a[1]), "r"(a[2]), "r"(a[3]), "r"(b[0]), "r"(b[1]));
}
__device__ __forceinline__ void split_bf16(float v, __nv_bfloat16& h, __nv_bfloat16& l) {
    h = __float2bfloat16_rn(v);
    l = __float2bfloat16_rn(v - __bfloat162float(h));
}

// ---------------- validated HMMA bf16x3 GEMM (round-10 mainloop, unchanged) ----
// EPI 1: h = leakyrelu(cemb @ W1c + g_hi[nn]+g_hj[mm]+bias) -> split planes  K=256
// EPI 0: [feat | rel | conf] = h @ Bcomb + g_bias2                           K=1024
#define TK2   16
#define APAD2 24
template<int EPI>
__global__ __launch_bounds__(256)
void mma_gemm(const float* __restrict__ bias,
              float* __restrict__ out_feat,
              float* __restrict__ out_rel)
{
    const __nv_bfloat16* __restrict__ Ahi = (EPI == 1) ? g_c_hi : g_hb_hi;
    const __nv_bfloat16* __restrict__ Alo = (EPI == 1) ? g_c_lo : g_hb_lo;
    const __nv_bfloat16* __restrict__ Bhi = (EPI == 1) ? g_W1t_hi : g_W2t_hi;
    const __nv_bfloat16* __restrict__ Blo = (EPI == 1) ? g_W1t_lo : g_W2t_lo;
    constexpr int K = (EPI == 1) ? C_EMB : H_DIM;
    constexpr int NC = K / TK2;

    __shared__ __align__(16) __nv_bfloat16 sAhi[2][128][APAD2];
    __shared__ __align__(16) __nv_bfloat16 sAlo[2][128][APAD2];
    __shared__ __align__(16) __nv_bfloat16 sBhi[2][128][APAD2];
    __shared__ __align__(16) __nv_bfloat16 sBlo[2][128][APAD2];

    const int tid = threadIdx.x;
    const int lane = tid & 31, wid = tid >> 5;
    const int m0 = blockIdx.y * 128, n0 = blockIdx.x * 128;

    const int m_base = (wid >> 2) * 64;
    const int n_base = (wid & 3) * 32;
    const int fr = lane >> 2;             // fragment row 0..7
    const int fk = (lane & 3) * 2;        // fragment k 0,2,4,6

    const int ld_row = tid >> 1, ld_c = (tid & 1) * 8;

    float acc[4][4][4];
#pragma unroll
    for (int i = 0; i < 4; i++)
#pragma unroll
        for (int j = 0; j < 4; j++)
#pragma unroll
            for (int r = 0; r < 4; r++) acc[i][j][r] = 0.f;

    // preload chunk 0 into buffer 0
    {
        const size_t ka = (size_t)(m0 + ld_row) * K + ld_c;
        const size_t kb = (size_t)(n0 + ld_row) * K + ld_c;
        *(uint4*)&sAhi[0][ld_row][ld_c] = *(const uint4*)(Ahi + ka);
        *(uint4*)&sAlo[0][ld_row][ld_c] = *(const uint4*)(Alo + ka);
        *(uint4*)&sBhi[0][ld_row][ld_c] = *(const uint4*)(Bhi + kb);
        *(uint4*)&sBlo[0][ld_row][ld_c] = *(const uint4*)(Blo + kb);
    }
    __syncthreads();

    for (int c = 0; c < NC; c++) {
        const int cur = c & 1, nxt = cur ^ 1;
        uint4 pa, pb, pc, pd;
        if (c + 1 < NC) {
            const size_t ka = (size_t)(m0 + ld_row) * K + (c + 1) * TK2 + ld_c;
            const size_t kb = (size_t)(n0 + ld_row) * K + (c + 1) * TK2 + ld_c;
            pa = *(const uint4*)(Ahi + ka);
            pb = *(const uint4*)(Alo + ka);
            pc = *(const uint4*)(Bhi + kb);
            pd = *(const uint4*)(Blo + kb);
        }

        uint32_t a_hi[4][4], a_lo[4][4], b_hi[4][2], b_lo[4][2];
#pragma unroll
        for (int mt = 0; mt < 4; mt++) {
            const int r0 = m_base + mt * 16 + fr;
            a_hi[mt][0] = *(const uint32_t*)&sAhi[cur][r0    ][fk];
            a_hi[mt][1] = *(const uint32_t*)&sAhi[cur][r0 + 8][fk];
            a_hi[mt][2] = *(const uint32_t*)&sAhi[cur][r0    ][fk + 8];
            a_hi[mt][3] = *(const uint32_t*)&sAhi[cur][r0 + 8][fk + 8];
            a_lo[mt][0] = *(const uint32_t*)&sAlo[cur][r0    ][fk];
            a_lo[mt][1] = *(const uint32_t*)&sAlo[cur][r0 + 8][fk];
            a_lo[mt][2] = *(const uint32_t*)&sAlo[cur][r0    ][fk + 8];
            a_lo[mt][3] = *(const uint32_t*)&sAlo[cur][r0 + 8][fk + 8];
        }
#pragma unroll
        for (int nt = 0; nt < 4; nt++) {
            const int n = n_base + nt * 8 + fr;
            b_hi[nt][0] = *(const uint32_t*)&sBhi[cur][n][fk];
            b_hi[nt][1] = *(const uint32_t*)&sBhi[cur][n][fk + 8];
            b_lo[nt][0] = *(const uint32_t*)&sBlo[cur][n][fk];
            b_lo[nt][1] = *(const uint32_t*)&sBlo[cur][n][fk + 8];
        }
#pragma unroll
        for (int mt = 0; mt < 4; mt++)
#pragma unroll
            for (int nt = 0; nt < 4; nt++) {
                mma_bf16(acc[mt][nt], a_hi[mt], b_hi[nt]);
                mma_bf16(acc[mt][nt], a_hi[mt], b_lo[nt]);
                mma_bf16(acc[mt][nt], a_lo[mt], b_hi[nt]);
            }

        if (c + 1 < NC) {
            *(uint4*)&sAhi[nxt][ld_row][ld_c] = pa;
            *(uint4*)&sAlo[nxt][ld_row][ld_c] = pb;
            *(uint4*)&sBhi[nxt][ld_row][ld_c] = pc;
            *(uint4*)&sBlo[nxt][ld_row][ld_c] = pd;
        }
        __syncthreads();
    }

    // epilogue: c0,c1 -> row fr; c2,c3 -> row fr+8
#pragma unroll
    for (int mt = 0; mt < 4; mt++)
#pragma unroll
        for (int nt = 0; nt < 4; nt++) {
            const int col0 = n0 + n_base + nt * 8 + fk;
#pragma unroll
            for (int half = 0; half < 2; half++) {
                const int row = m0 + m_base + mt * 16 + fr + half * 8;
                float v0 = acc[mt][nt][half * 2];
                float v1 = acc[mt][nt][half * 2 + 1];
                if (EPI == 1) {
                    const int nn = row >> 8, mm = row & 255;
                    v0 += g_hi[nn * H_DIM + col0]     + g_hj[mm * H_DIM + col0]     + bias[col0];
                    v1 += g_hi[nn * H_DIM + col0 + 1] + g_hj[mm * H_DIM + col0 + 1] + bias[col0 + 1];
                    v0 = (v0 >= 0.f) ? v0 : SLOPE * v0;
                    v1 = (v1 >= 0.f) ? v1 : SLOPE * v1;
                    __nv_bfloat16 h0, l0, h1, l1;
                    split_bf16(v0, h0, l0);
                    split_bf16(v1, h1, l1);
                    const size_t o = (size_t)row * H_DIM + col0;
                    *(__nv_bfloat162*)(g_hb_hi + o) = __nv_bfloat162(h0, h1);
                    *(__nv_bfloat162*)(g_hb_lo + o) = __nv_bfloat162(l0, l1);
                } else {
                    v0 += g_bias2[col0];
                    v1 += g_bias2[col0 + 1];
                    if (blockIdx.x < 8) {
                        *(float2*)(out_feat + (size_t)row * O_DIM + col0) = make_float2(v0, v1);
                    } else {
                        const int j0 = col0 - 1024;   // even
                        if (j0 < R_DIM)           out_rel[(size_t)row * R_DIM + j0] = v0;
                        if (j0 + 1 < R_DIM)       out_rel[(size_t)row * R_DIM + j0 + 1] = v1;
                        else if (j0 + 1 == R_DIM) g_conf[row] = v1;
                    }
                }
            }
        }
}

// ---------------- hi/hj: K-split fp32 GEMM (128 blocks) + reduce ---------------
__launch_bounds__(256)
__global__ void gemm_hij(const float* __restrict__ feats, const float* __restrict__ W1)
{
    const int which = blockIdx.z >> 2;
    const int kc = blockIdx.z & 3;
    __shared__ float As[8][132];
    __shared__ float Bs[8][128];
    const int tid = threadIdx.x;
    const int tx = tid & 15, ty = tid >> 4;
    const int m0 = blockIdx.y * 128, n0 = blockIdx.x * 128;
    float acc[8][8];
#pragma unroll
    for (int i = 0; i < 8; i++)
#pragma unroll
        for (int j = 0; j < 8; j++) acc[i][j] = 0.f;
    const int ar = tid >> 1, ak = (tid & 1) * 4;
    const int bk = tid >> 5, bc = (tid & 31) * 4;
    const float* Aptr = feats + (size_t)(m0 + ar) * 1024 + kc * 256 + ak;
    const float* Bptr = W1 + (size_t)(which * D_IN + kc * 256 + bk) * 1024 + n0 + bc;
    for (int k0 = 0; k0 < 256; k0 += 8) {
        float4 av = *(const float4*)(Aptr + k0);
        float4 bv = *(const float4*)(Bptr + (size_t)k0 * 1024);
        As[ak][ar] = av.x; As[ak + 1][ar] = av.y; As[ak + 2][ar] = av.z; As[ak + 3][ar] = av.w;
        *(float4*)(&Bs[bk][bc]) = bv;
        __syncthreads();
#pragma unroll
        for (int kk = 0; kk < 8; kk++) {
            float a[8], b[8];
#pragma unroll
            for (int i = 0; i < 8; i++) a[i] = As[kk][ty * 8 + i];
#pragma unroll
            for (int j = 0; j < 8; j++) b[j] = Bs[kk][tx * 8 + j];
#pragma unroll
            for (int i = 0; i < 8; i++)
#pragma unroll
                for (int j = 0; j < 8; j++) acc[i][j] += a[i] * b[j];
        }
        __syncthreads();
    }
    float* dst = g_part + (size_t)blockIdx.z * N_OBJ * H_DIM;
#pragma unroll
    for (int i = 0; i < 8; i++)
#pragma unroll
        for (int j = 0; j < 8; j++)
            dst[(size_t)(m0 + ty * 8 + i) * 1024 + n0 + tx * 8 + j] = acc[i][j];
}

__global__ void reduce_hij()
{
    const int idx = blockIdx.x * 256 + threadIdx.x;
    const int which = idx >> 18;
    const int base = idx & (N_OBJ * H_DIM - 1);
    const size_t stride = (size_t)N_OBJ * H_DIM;
    const float* p = g_part + (size_t)which * 4 * stride + base;
    const float s = p[0] + p[stride] + p[2 * stride] + p[3 * stride];
    if (which == 0) g_hi[base] = s;
    else            g_hj[base] = s;
}

// ---------------- converters ---------------------------------------------------
__global__ void convert_cemb(const float* __restrict__ in)
{
    const size_t i = ((size_t)blockIdx.x * 256 + threadIdx.x) * 4;
    if (i >= (size_t)NP * C_EMB) return;
    const float4 v4 = *(const float4*)(in + i);
    const float v[4] = { v4.x, v4.y, v4.z, v4.w };
    uint32_t hw[2], lw[2];
#pragma unroll
    for (int p = 0; p < 2; p++) {
        __nv_bfloat16 h0, l0, h1, l1;
        split_bf16(v[2 * p], h0, l0);
        split_bf16(v[2 * p + 1], h1, l1);
        hw[p] = (uint32_t)__bfloat16_as_ushort(h0) | ((uint32_t)__bfloat16_as_ushort(h1) << 16);
        lw[p] = (uint32_t)__bfloat16_as_ushort(l0) | ((uint32_t)__bfloat16_as_ushort(l1) << 16);
    }
    *(uint2*)((char*)g_c_hi + i * 2) = make_uint2(hw[0], hw[1]);
    *(uint2*)((char*)g_c_lo + i * 2) = make_uint2(lw[0], lw[1]);
}

// W1c^T split via 32x32 tiled transpose. grid (C_EMB/32, H_DIM/32), 256 thr.
__global__ void split_W1t(const float* __restrict__ W1)
{
    __shared__ float t[32][33];
    const int kb = blockIdx.x * 32;
    const int jb = blockIdx.y * 32;
    const int tx = threadIdx.x & 31, ty = threadIdx.x >> 5;
#pragma unroll
    for (int r = 0; r < 4; r++) {
        const int k = kb + ty + r * 8;
        t[ty + r * 8][tx] = W1[(size_t)(2 * D_IN + k) * H_DIM + jb + tx];
    }
    __syncthreads();
#pragma unroll
    for (int r = 0; r < 4; r++) {
        const int j = jb + ty + r * 8;
        const int k = kb + tx;
        __nv_bfloat16 h, l;
        split_bf16(t[tx][ty + r * 8], h, l);
        g_W1t_hi[(size_t)j * C_EMB + k] = h;
        g_W1t_lo[(size_t)j * C_EMB + k] = l;
    }
}

// wrelc = W2 @ W_rel [1024,51], wattc = W2 @ w_att [1024]  (one block per k-row)
__global__ void small_mats(const float* __restrict__ W2, const float* __restrict__ Wrel,
                           const float* __restrict__ watt)
{
    __shared__ float row[1024];
    const int i = blockIdx.x, tid = threadIdx.x;
    for (int o = tid; o < 1024; o += 256) row[o] = W2[(size_t)i * O_DIM + o];
    __syncthreads();
    if (tid < R_DIM) {
        float s = 0.f;
        for (int o = 0; o < 1024; o++) s += row[o] * Wrel[(size_t)o * R_DIM + tid];
        g_wrelc[i * R_DIM + tid] = s;
    } else if (tid == R_DIM) {
        float s = 0.f;
        for (int o = 0; o < 1024; o++) s += row[o] * watt[o];
        g_wattc[i] = s;
    }
}

// (scale.W2)^T split via 32x32 tiled transpose (cols 0..1023)
__global__ void build_W2ts(const float* __restrict__ W2)
{
    __shared__ float t[32][33];
    const int kb = blockIdx.x * 32;
    const int jb = blockIdx.y * 32;
    const int tx = threadIdx.x & 31, ty = threadIdx.x >> 5;
#pragma unroll
    for (int r = 0; r < 4; r++) {
        const int k = kb + ty + r * 8;
        t[ty + r * 8][tx] = W2[(size_t)k * O_DIM + jb + tx];
    }
    __syncthreads();
#pragma unroll
    for (int r = 0; r < 4; r++) {
        const int j = jb + ty + r * 8;
        const int k = kb + tx;
        __nv_bfloat16 h, l;
        split_bf16(g_scale[k] * t[tx][ty + r * 8], h, l);
        g_W2t_hi[(size_t)j * H_DIM + k] = h;
        g_W2t_lo[(size_t)j * H_DIM + k] = l;
    }
}

// extra B^T columns 1024..1151: rel (scale.wrelc), conf (scale.wattc), zero pad
// grid (128, 4), 256 threads: j = 1024+bx, k = by*256+tid
__global__ void build_Bextra()
{
    const int j = 1024 + blockIdx.x;
    const int k = blockIdx.y * 256 + threadIdx.x;
    const int j0 = j - 1024;
    float w = 0.f;
    if (j0 < R_DIM)       w = g_scale[k] * g_wrelc[k * R_DIM + j0];
    else if (j0 == R_DIM) w = g_scale[k] * g_wattc[k];
    __nv_bfloat16 h, l;
    split_bf16(w, h, l);
    g_W2t_hi[(size_t)j * H_DIM + k] = h;
    g_W2t_lo[(size_t)j * H_DIM + k] = l;
}

// bias2[j<1024] = b2[j] + sum_k shift[k] * W2[k][j]
__global__ void build_bias2(const float* __restrict__ W2, const float* __restrict__ b2)
{
    const int j = blockIdx.x * 256 + threadIdx.x;
    float s = b2[j];
#pragma unroll 4
    for (int k = 0; k < H_DIM; k++)
        s += g_shift[k] * W2[(size_t)k * O_DIM + j];
    g_bias2[j] = s;
}

// bias2[1024+j0]: rel -> bias2[:1024]@Wrel + brel ; conf -> bias2.watt + batt ; 0 pad
// grid 128 blocks, 256 threads, shared reduce (runs AFTER build_bias2)
__global__ void build_biasX(const float* __restrict__ Wrel, const float* __restrict__ brel,
                            const float* __restrict__ watt, const float* __restrict__ batt)
{
    __shared__ float red[256];
    const int j0 = blockIdx.x, tid = threadIdx.x;
    float a = 0.f;
    if (j0 < R_DIM) {
        for (int o = tid; o < 1024; o += 256) a += g_bias2[o] * Wrel[(size_t)o * R_DIM + j0];
    } else if (j0 == R_DIM) {
        for (int o = tid; o < 1024; o += 256) a += g_bias2[o] * watt[o];
    }
    red[tid] = a;
    __syncthreads();
    for (int o = 128; o; o >>= 1) {
        if (tid < o) red[tid] += red[tid + o];
        __syncthreads();
    }
    if (tid == 0) {
        float b = 0.f;
        if (j0 < R_DIM)       b = red[0] + brel[j0];
        else if (j0 == R_DIM) b = red[0] + batt[0];
        g_bias2[1024 + j0] = b;
    }
}

// ---------------- BN stats from split planes (deterministic) -------------------
__global__ void stats_planes()
{
    const int cp = blockIdx.x * 256 + threadIdx.x;
    const int rb = blockIdx.y;
    const int c0 = cp * 2;
    float s0 = 0.f, s1 = 0.f, q0 = 0.f, q1 = 0.f;
#pragma unroll 4
    for (int r = 0; r < 256; r++) {
        const size_t o = (size_t)(rb * 256 + r) * H_DIM + c0;
        const __nv_bfloat162 h2 = *(const __nv_bfloat162*)(g_hb_hi + o);
        const __nv_bfloat162 l2 = *(const __nv_bfloat162*)(g_hb_lo + o);
        const float v0 = __bfloat162float(h2.x) + __bfloat162float(l2.x);
        const float v1 = __bfloat162float(h2.y) + __bfloat162float(l2.y);
        s0 += v0; q0 += v0 * v0;
        s1 += v1; q1 += v1 * v1;
    }
    g_ps[rb * H_DIM + c0] = s0; g_ps[rb * H_DIM + c0 + 1] = s1;
    g_pq[rb * H_DIM + c0] = q0; g_pq[rb * H_DIM + c0 + 1] = q1;
}

__global__ void finalize_bn(const float* __restrict__ gamma, const float* __restrict__ beta)
{
    const int c = blockIdx.x * 256 + threadIdx.x;
    float s = 0.f, q = 0.f;
#pragma unroll
    for (int i = 0; i < RB_STATS; i++) { s += g_ps[i * H_DIM + c]; q += g_pq[i * H_DIM + c]; }
    const float inv = 1.0f / (float)NP;
    const float mean = s * inv;
    const float var = q * inv - mean * mean;
    const float sc = gamma[c] * rsqrtf(var + BN_EPS);
    g_scale[c] = sc;
    g_shift[c] = beta[c] - mean * sc;
}

// ---------------- softmax + weighted aggregation -------------------------------
__global__ void attn_agg(const float* __restrict__ feat, float* __restrict__ enhanced)
{
    __shared__ float conf[N_OBJ];
    __shared__ float red[256];
    const int n = blockIdx.x, tid = threadIdx.x;
    const int c0 = blockIdx.y * 256;
    const float v = g_conf[n * N_OBJ + tid];
    red[tid] = v;
    __syncthreads();
    for (int o = 128; o; o >>= 1) {
        if (tid < o) red[tid] = fmaxf(red[tid], red[tid + o]);
        __syncthreads();
    }
    const float mx = red[0];
    __syncthreads();
    const float e = expf(v - mx);
    red[tid] = e;
    __syncthreads();
    for (int o = 128; o; o >>= 1) {
        if (tid < o) red[tid] += red[tid + o];
        __syncthreads();
    }
    const float p = e / red[0];
    __syncthreads();
    conf[tid] = p;
    __syncthreads();

    float acc = 0.f;
    const float* base = feat + (size_t)n * N_OBJ * O_DIM + c0 + tid;
#pragma unroll 4
    for (int m = 0; m < N_OBJ; m++)
        acc += conf[m] * base[(size_t)m * O_DIM];
    enhanced[(size_t)n * O_DIM + c0 + tid] = acc;
}

// ---------------- launcher ------------------------------------------------------
// NOTE: every kernel argument below is a d_in/d_out pointer. Device scratch is
// reached only through device-code symbol references.
extern "C" void kernel_launch(void* const* d_in, const int* in_sizes, int n_in,
                              void* d_out, int out_size)
{
    const float* feats = (const float*)d_in[0];
    const float* cemb  = (const float*)d_in[1];
    const float* W1    = (const float*)d_in[2];
    const float* b1    = (const float*)d_in[3];
    const float* gamma = (const float*)d_in[4];
    const float* beta  = (const float*)d_in[5];
    const float* W2    = (const float*)d_in[6];
    const float* b2    = (const float*)d_in[7];
    const float* watt  = (const float*)d_in[8];
    const float* batt  = (const float*)d_in[9];
    const float* Wrel  = (const float*)d_in[10];
    const float* brel  = (const float*)d_in[11];

    float* out      = (float*)d_out;
    float* feat     = out;
    float* enhanced = out + (size_t)NP * O_DIM;
    float* relation = enhanced + (size_t)N_OBJ * O_DIM;

    // converters + small mats (independent of GEMMs)
    convert_cemb<<<(int)(((size_t)NP * C_EMB / 4 + 255) / 256), 256>>>(cemb);
    split_W1t<<<dim3(C_EMB / 32, H_DIM / 32), 256>>>(W1);
    small_mats<<<H_DIM, 256>>>(W2, Wrel, watt);

    // hi/hj: K-split GEMM + deterministic reduce
    gemm_hij<<<dim3(8, 2, 8), 256>>>(feats, W1);
    reduce_hij<<<2 * N_OBJ * H_DIM / 256, 256>>>();

    // GEMM1 (HMMA): h = leakyrelu(cemb @ W1c + hi + hj + b1) -> split planes
    mma_gemm<1><<<dim3(8, 512), 256>>>(b1, nullptr, nullptr);

    // BN stats + fold into combined B / bias
    stats_planes<<<dim3(2, RB_STATS), 256>>>();
    finalize_bn<<<4, 256>>>(gamma, beta);
    build_W2ts<<<dim3(H_DIM / 32, O_DIM / 32), 256>>>(W2);
    build_Bextra<<<dim3(128, 4), 256>>>();
    build_bias2<<<O_DIM / 256, 256>>>(W2, b2);
    build_biasX<<<128, 256>>>(Wrel, brel, watt, batt);

    // GEMM2 (HMMA): [feat | relation | conf] = h @ Bcomb + bias2
    mma_gemm<0><<<dim3(9, 512), 256>>>(nullptr, feat, relation);

    // attention softmax + aggregation (logits from GEMM2)
    attn_agg<<<dim3(N_OBJ, 4), 256>>>(feat, enhanced);
}